// round 15
// baseline (speedup 1.0000x reference)
#include <cuda_runtime.h>
#include <cuda_bf16.h>
#include <math.h>
#include <stdint.h>

#define BB   4
#define CC   2048
#define PP   196
#define BP   784
#define NCN  200
#define WDD  300
#define INTD 1024
#define NEE  800
#define NL   3
#define EPSV 1e-5f

#define MROWS (BB*NCN)               // 800
#define WSLOT ((size_t)CC*CC)
#define XSLOT ((size_t)MROWS*CC)
#define W1OFF ((size_t)27*WSLOT)

// ---------------- scratch ----------------
__device__ float g_fmap[BP * CC];
__device__ __nv_bfloat16 g_fmh[BP * CC];
__device__ __nv_bfloat16 g_fml[BP * CC];
__device__ float g_fwh [BP * INTD];
__device__ float g_fwd [NCN * INTD];
__device__ float g_wpart[16 * INTD];
__device__ float g_weff[INTD];
__device__ float g_ceff[1];
__device__ float g_coef[BP * NCN];
__device__ float g_x   [XSLOT];
__device__ __nv_bfloat16 g_xh[XSLOT];
__device__ __nv_bfloat16 g_xl[XSLOT];
__device__ float g_h   [XSLOT];
__device__ float g_t   [5 * XSLOT];
__device__ float g_mean[CC];
__device__ float g_var [CC];
__device__ int   g_es  [NEE];
__device__ int   g_ee  [NEE];
__device__ int   g_eoff[NCN + 1];
__device__ int   g_elist[NEE];
__device__ __nv_bfloat16 g_wbh[27 * WSLOT + (size_t)INTD * CC];
__device__ __nv_bfloat16 g_wbl[27 * WSLOT + (size_t)INTD * CC];

__device__ __forceinline__ float sigm(float x) {
    return 1.0f / (1.0f + __expf(-x));
}

__device__ __forceinline__ float fast_tanh(float x) {
    float t = fminf(fmaxf(x, -8.0f), 8.0f);
    float z = t * 2.8853900817779268f;
    float zr = z + 12582912.0f;
    int   j  = __float_as_int(zr) - 0x4B400000;
    float f  = z - (zr - 12582912.0f);
    float p = 0.0096181291f;
    p = fmaf(p, f, 0.0555041087f);
    p = fmaf(p, f, 0.2402265069f);
    p = fmaf(p, f, 0.6931471806f);
    p = fmaf(p, f, 1.0f);
    float s = __int_as_float((j + 127) << 23);
    float e = p * s;
    float u = e + 1.0f;
    float r = __int_as_float(0x7EF311C3 - __float_as_int(u));
    r = r * fmaf(-u, r, 2.0f);
    r = r * fmaf(-u, r, 2.0f);
    return (e - 1.0f) * r;
}

__device__ __forceinline__ uint32_t smem_u32(const void* p) {
    uint32_t a;
    asm("{ .reg .u64 t; cvta.to.shared.u64 t, %1; cvt.u32.u64 %0, t; }"
        : "=r"(a) : "l"(p));
    return a;
}

#define LDSM4(R, addr) \
    asm volatile("ldmatrix.sync.aligned.m8n8.x4.shared.b16 {%0,%1,%2,%3}, [%4];" \
        : "=r"((R)[0]), "=r"((R)[1]), "=r"((R)[2]), "=r"((R)[3]) : "r"(addr))

#define MMA16816(C, A, B0, B1) \
    asm volatile("mma.sync.aligned.m16n8k16.row.col.f32.bf16.bf16.f32 " \
        "{%0,%1,%2,%3},{%4,%5,%6,%7},{%8,%9},{%0,%1,%2,%3};" \
        : "+f"((C)[0]), "+f"((C)[1]), "+f"((C)[2]), "+f"((C)[3]) \
        : "r"((A)[0]), "r"((A)[1]), "r"((A)[2]), "r"((A)[3]), "r"(B0), "r"(B1))

#define CP_ASYNC16(dst, src, vld) \
    asm volatile("cp.async.cg.shared.global [%0], [%1], 16, %2;" \
        :: "r"(dst), "l"(src), "r"(vld))
#define CP_COMMIT() asm volatile("cp.async.commit_group;" ::: "memory")
#define CP_WAIT1()  asm volatile("cp.async.wait_group 1;" ::: "memory")
#define CP_WAIT0()  asm volatile("cp.async.wait_group 0;" ::: "memory")

// ============================ HMMA GEMM ======================================
// 128x256 block tile, 8 warps (2x4) of 64x64, XOR-swizzled 64B rows,
// 3-stage cp.async, ONE barrier per chunk, 1 CTA/SM.
#define TM 128
#define TN 256
#define TK 32
#define A_SZ  (128 * 64)               // 8192
#define B_SZ  (256 * 64)               // 16384
#define STAGE (2 * A_SZ + 2 * B_SZ)    // 49152
#define NSTG  3
#define SMTOT (NSTG * STAGE)           // 147456

__device__ __forceinline__ uint32_t swz_off(int row, int g) {
    return (uint32_t)(row * 64 + ((g ^ ((row >> 1) & 3)) << 4));
}

__global__ void __launch_bounds__(256, 1) k_tgemm(
    const __nv_bfloat16* __restrict__ Ah, const __nv_bfloat16* __restrict__ Al,
    const __nv_bfloat16* __restrict__ Wh, const __nv_bfloat16* __restrict__ Wl,
    float* __restrict__ out, int M, int K, int nPerW, int ntilesPerW,
    int nchPerZ, size_t zStride)
{
    extern __shared__ char smem[];
    const uint32_t sbase = smem_u32(smem);
    const int tid  = threadIdx.x;
    const int lane = tid & 31, wid = tid >> 5;
    const int wm = wid >> 2, wn = wid & 3;        // 2 x 4 warps of 64x64
    const int widx = blockIdx.x / ntilesPerW;
    const int nt   = blockIdx.x % ntilesPerW;
    const int bm   = blockIdx.y * TM;
    const int kb0  = blockIdx.z * nchPerZ * TK;
    const __nv_bfloat16* Wbh = Wh + (size_t)widx * nPerW * K + (size_t)nt * TN * K;
    const __nv_bfloat16* Wbl = Wl + (size_t)widx * nPerW * K + (size_t)nt * TN * K;
    float* outp = out + (size_t)blockIdx.z * zStride
                      + (size_t)widx * M * nPerW + (size_t)nt * TN;

    float acc[4][8][4];
#pragma unroll
    for (int a = 0; a < 4; a++)
#pragma unroll
        for (int b = 0; b < 8; b++)
#pragma unroll
            for (int c = 0; c < 4; c++) acc[a][b][c] = 0.0f;

    auto load_stage = [&](int ch, int st) {
        const uint32_t so = sbase + st * STAGE;
        const int kb = kb0 + ch * TK;
#pragma unroll
        for (int it = 0; it < 12; it++) {
            int idx = tid + it * 256;
            const __nv_bfloat16* src;
            uint32_t dst;
            int vld = 16;
            if (idx < 1024) {                          // A: Ah then Al
                int matA = idx >> 9;
                int r = (idx >> 2) & 127;
                int q = idx & 3;
                int gr = bm + r;
                if (gr >= M) { vld = 0; gr = M - 1; }
                src = (matA ? Al : Ah) + (size_t)gr * K + kb + q * 8;
                dst = so + matA * A_SZ + swz_off(r, q);
            } else {                                   // B: Bh then Bl
                int jj = idx - 1024;
                int matB = jj >> 10;
                int r = (jj >> 2) & 255;
                int q = jj & 3;
                src = (matB ? Wbl : Wbh) + (size_t)r * K + kb + q * 8;
                dst = so + 2 * A_SZ + matB * B_SZ + swz_off(r, q);
            }
            CP_ASYNC16(dst, src, vld);
        }
        CP_COMMIT();
    };

    const int a_row0 = wm * 64 + (lane & 15);
    const int a_g    = lane >> 4;
    const int b_row0 = wn * 64 + (lane & 7) + ((lane & 16) ? 8 : 0);
    const int b_g    = (lane & 8) ? 1 : 0;

    auto compute_stage = [&](int st) {
        const uint32_t so = sbase + st * STAGE;
#pragma unroll
        for (int ks = 0; ks < 2; ks++) {
            uint32_t bh[4][4], bl[4][4];
#pragma unroll
            for (int p = 0; p < 4; p++) {
                int row = b_row0 + p * 16;
                uint32_t bd = so + 2 * A_SZ + swz_off(row, ks * 2 + b_g);
                LDSM4(bh[p], bd);
                LDSM4(bl[p], bd + B_SZ);
            }
#pragma unroll
            for (int im = 0; im < 4; im++) {
                int row = a_row0 + im * 16;
                uint32_t ad = so + swz_off(row, ks * 2 + a_g);
                uint32_t ah[4], al[4];
                LDSM4(ah, ad);
                LDSM4(al, ad + A_SZ);
#pragma unroll
                for (int in = 0; in < 8; in++) {
                    int p = in >> 1, s2 = (in & 1) * 2;
                    MMA16816(acc[im][in], ah, bh[p][s2], bh[p][s2 + 1]);
                    MMA16816(acc[im][in], ah, bl[p][s2], bl[p][s2 + 1]);
                    MMA16816(acc[im][in], al, bh[p][s2], bh[p][s2 + 1]);
                }
            }
        }
    };

    const int nch = nchPerZ;
    load_stage(0, 0);
    if (nch > 1) load_stage(1, 1);
    for (int ch = 0; ch < nch; ch++) {
        if (ch + 1 < nch) { CP_WAIT1(); } else { CP_WAIT0(); }
        __syncthreads();
        if (ch + 2 < nch) load_stage(ch + 2, (ch + 2) % NSTG);
        compute_stage(ch % NSTG);
    }

#pragma unroll
    for (int im = 0; im < 4; im++) {
        int r0 = bm + wm * 64 + im * 16 + (lane >> 2);
#pragma unroll
        for (int in = 0; in < 8; in++) {
            int col = wn * 64 + (in >> 1) * 16 + (in & 1) * 8 + (lane & 3) * 2;
            if (r0 < M) {
                float2 v; v.x = acc[im][in][0]; v.y = acc[im][in][1];
                *reinterpret_cast<float2*>(outp + (size_t)r0 * nPerW + col) = v;
            }
            if (r0 + 8 < M) {
                float2 v; v.x = acc[im][in][2]; v.y = acc[im][in][3];
                *reinterpret_cast<float2*>(outp + (size_t)(r0 + 8) * nPerW + col) = v;
            }
        }
    }
}

// split-K reduce for W1
__global__ void k_red4() {
    int i = blockIdx.x * 256 + threadIdx.x;
    const int S4 = BP * INTD / 4;
    if (i >= S4) return;
    const float4* t = reinterpret_cast<const float4*>(g_t);
    float4 a = t[i], b = t[S4 + i], c = t[2 * S4 + i], d = t[3 * S4 + i];
    float4 r;
    r.x = (a.x + b.x) + (c.x + d.x);
    r.y = (a.y + b.y) + (c.y + d.y);
    r.z = (a.z + b.z) + (c.z + d.z);
    r.w = (a.w + b.w) + (c.w + d.w);
    reinterpret_cast<float4*>(g_fwh)[i] = r;
}

// ============================ small kernels ==================================

struct WP27 { const float4* p[27]; };

__device__ __forceinline__ void split4(float4 v, uint2& h2, uint2& l2) {
    __nv_bfloat16 hx = __float2bfloat16(v.x);
    __nv_bfloat16 hy = __float2bfloat16(v.y);
    __nv_bfloat16 hz = __float2bfloat16(v.z);
    __nv_bfloat16 hw = __float2bfloat16(v.w);
    __nv_bfloat162 a = __halves2bfloat162(hx, hy);
    __nv_bfloat162 b = __halves2bfloat162(hz, hw);
    h2.x = *reinterpret_cast<uint32_t*>(&a);
    h2.y = *reinterpret_cast<uint32_t*>(&b);
    __nv_bfloat162 c = __halves2bfloat162(
        __float2bfloat16(v.x - __bfloat162float(hx)),
        __float2bfloat16(v.y - __bfloat162float(hy)));
    __nv_bfloat162 d = __halves2bfloat162(
        __float2bfloat16(v.z - __bfloat162float(hz)),
        __float2bfloat16(v.w - __bfloat162float(hw)));
    l2.x = *reinterpret_cast<uint32_t*>(&c);
    l2.y = *reinterpret_cast<uint32_t*>(&d);
}

__global__ void k_convall(WP27 w) {
    int slot = blockIdx.y;
    size_t i = ((size_t)blockIdx.x * 256 + threadIdx.x) * 4;
    const float4* src = w.p[slot];
    float4 v0 = __ldcs(src + i);
    float4 v1 = __ldcs(src + i + 1);
    float4 v2 = __ldcs(src + i + 2);
    float4 v3 = __ldcs(src + i + 3);
    uint4 ho0, lo0, ho1, lo1;
    uint2 h2, l2;
    split4(v0, h2, l2); ho0.x = h2.x; ho0.y = h2.y; lo0.x = l2.x; lo0.y = l2.y;
    split4(v1, h2, l2); ho0.z = h2.x; ho0.w = h2.y; lo0.z = l2.x; lo0.w = l2.y;
    split4(v2, h2, l2); ho1.x = h2.x; ho1.y = h2.y; lo1.x = l2.x; lo1.y = l2.y;
    split4(v3, h2, l2); ho1.z = h2.x; ho1.w = h2.y; lo1.z = l2.x; lo1.w = l2.y;
    size_t base = (size_t)slot * WSLOT / 8 + i / 2;
    __stcs(reinterpret_cast<uint4*>(g_wbh) + base,     ho0);
    __stcs(reinterpret_cast<uint4*>(g_wbh) + base + 1, ho1);
    __stcs(reinterpret_cast<uint4*>(g_wbl) + base,     lo0);
    __stcs(reinterpret_cast<uint4*>(g_wbl) + base + 1, lo1);
}

__global__ void k_conv(const float4* __restrict__ src,
                       __nv_bfloat16* __restrict__ dh,
                       __nv_bfloat16* __restrict__ dl, int n4)
{
    int i = (blockIdx.x * blockDim.x + threadIdx.x) * 2;
    if (i >= n4) return;
    float4 v0 = __ldcs(src + i);
    float4 v1 = __ldcs(src + i + 1);
    uint4 ho, lo;
    uint2 h2, l2;
    split4(v0, h2, l2); ho.x = h2.x; ho.y = h2.y; lo.x = l2.x; lo.y = l2.y;
    split4(v1, h2, l2); ho.z = h2.x; ho.w = h2.y; lo.z = l2.x; lo.w = l2.y;
    __stcs(reinterpret_cast<uint4*>(dh) + i / 2, ho);
    __stcs(reinterpret_cast<uint4*>(dl) + i / 2, lo);
}

__global__ void k_transpose(const float* __restrict__ img) {
    __shared__ float tile[32][33];
    int b  = blockIdx.z;
    int p0 = blockIdx.x * 32;
    int c0 = blockIdx.y * 32;
    int tx = threadIdx.x, ty = threadIdx.y;
#pragma unroll
    for (int j = 0; j < 4; j++) {
        int c = c0 + ty + j * 8;
        int p = p0 + tx;
        float v = (p < PP) ? img[((size_t)b * CC + c) * PP + p] : 0.0f;
        tile[ty + j * 8][tx] = v;
    }
    __syncthreads();
#pragma unroll
    for (int j = 0; j < 4; j++) {
        int p = p0 + ty + j * 8;
        int c = c0 + tx;
        if (p < PP) {
            float v = tile[tx][ty + j * 8];
            size_t o = ((size_t)b * PP + p) * CC + c;
            g_fmap[o] = v;
            __nv_bfloat16 h = __float2bfloat16(v);
            g_fmh[o] = h;
            g_fml[o] = __float2bfloat16(v - __bfloat162float(h));
        }
    }
}

__global__ __launch_bounds__(256) void k_sgemm(
    const float* __restrict__ A, const float* __restrict__ W,
    float* __restrict__ C, int M, int N, int K)
{
    __shared__ float As[16][65];
    __shared__ float Bs[16][65];
    const int tid = threadIdx.x;
    const int tx = tid & 15, ty = tid >> 4;
    const int bm = blockIdx.y * 64, bn = blockIdx.x * 64;
    const int lr = tid >> 2;
    const int lk = (tid & 3) << 2;

    float acc[4][4];
#pragma unroll
    for (int i = 0; i < 4; i++)
#pragma unroll
        for (int j = 0; j < 4; j++) acc[i][j] = 0.0f;

    for (int k0 = 0; k0 < K; k0 += 16) {
        float a0 = 0, a1 = 0, a2 = 0, a3 = 0;
        int arow = bm + lr;
        if (arow < M) {
            const float* ap = A + (size_t)arow * K + k0 + lk;
            if (k0 + lk + 0 < K) a0 = ap[0];
            if (k0 + lk + 1 < K) a1 = ap[1];
            if (k0 + lk + 2 < K) a2 = ap[2];
            if (k0 + lk + 3 < K) a3 = ap[3];
        }
        As[lk + 0][lr] = a0; As[lk + 1][lr] = a1;
        As[lk + 2][lr] = a2; As[lk + 3][lr] = a3;

        float b0 = 0, b1 = 0, b2 = 0, b3 = 0;
        int wrow = bn + lr;
        if (wrow < N) {
            const float* wp = W + (size_t)wrow * K + k0 + lk;
            if (k0 + lk + 0 < K) b0 = wp[0];
            if (k0 + lk + 1 < K) b1 = wp[1];
            if (k0 + lk + 2 < K) b2 = wp[2];
            if (k0 + lk + 3 < K) b3 = wp[3];
        }
        Bs[lk + 0][lr] = b0; Bs[lk + 1][lr] = b1;
        Bs[lk + 2][lr] = b2; Bs[lk + 3][lr] = b3;

        __syncthreads();
#pragma unroll
        for (int k = 0; k < 16; k++) {
            float av[4], bv[4];
#pragma unroll
            for (int i = 0; i < 4; i++) av[i] = As[k][ty * 4 + i];
#pragma unroll
            for (int j = 0; j < 4; j++) bv[j] = Bs[k][tx * 4 + j];
#pragma unroll
            for (int i = 0; i < 4; i++)
#pragma unroll
                for (int j = 0; j < 4; j++) acc[i][j] += av[i] * bv[j];
        }
        __syncthreads();
    }
#pragma unroll
    for (int i = 0; i < 4; i++) {
        int r = bm + ty * 4 + i;
        if (r >= M) continue;
#pragma unroll
        for (int j = 0; j < 4; j++) {
            int cI = bn + tx * 4 + j;
            if (cI < N) C[(size_t)r * N + cI] = acc[i][j];
        }
    }
}

__global__ void k_weff1(const float* __restrict__ W3, const float* __restrict__ Wa) {
    int i = blockIdx.x * 256 + threadIdx.x;
    int oc = blockIdx.y;
    float s = 0.0f;
    for (int o = oc * 64; o < (oc + 1) * 64; o++)
        s += Wa[o] * W3[(size_t)o * INTD + i];
    g_wpart[oc * INTD + i] = s;
}
__global__ void k_weff2() {
    int i = blockIdx.x * 256 + threadIdx.x;
    float s = 0.0f;
#pragma unroll
    for (int oc = 0; oc < 16; oc++) s += g_wpart[oc * INTD + i];
    g_weff[i] = s;
}

__global__ void k_ceff(const float* __restrict__ Wa, const float* __restrict__ b3,
                       const float* __restrict__ ba) {
    __shared__ float red[256];
    int tid = threadIdx.x;
    float s = 0.0f;
    for (int i = tid; i < INTD; i += 256) s += Wa[i] * b3[i];
    red[tid] = s; __syncthreads();
    for (int st = 128; st > 0; st >>= 1) {
        if (tid < st) red[tid] += red[tid + st];
        __syncthreads();
    }
    if (tid == 0) g_ceff[0] = red[0] + ba[0];
}

__global__ __launch_bounds__(256) void k_coef() {
    int bp = blockIdx.x;
    int tid = threadIdx.x;
    __shared__ float s_fwh[INTD];
    __shared__ float s_wef[INTD];
    for (int i = tid; i < INTD; i += 256) {
        s_fwh[i] = g_fwh[(size_t)bp * INTD + i];
        s_wef[i] = g_weff[i];
    }
    __syncthreads();
    int warp = tid >> 5, lane = tid & 31;
    float ce = g_ceff[0];
    for (int n = warp; n < NCN; n += 8) {
        const float* fw = g_fwd + (size_t)n * INTD;
        float acc = 0.0f;
        for (int i = lane; i < INTD; i += 32)
            acc += fast_tanh(s_fwh[i] * fw[i]) * s_wef[i];
#pragma unroll
        for (int off = 16; off > 0; off >>= 1)
            acc += __shfl_down_sync(0xffffffffu, acc, off);
        if (lane == 0) g_coef[(size_t)bp * NCN + n] = acc + ce;
    }
}

__global__ __launch_bounds__(256) void k_softmax() {
    int n = blockIdx.x, b = blockIdx.y;
    int tid = threadIdx.x;
    __shared__ float red[256];
    __shared__ float s_mx, s_sum;
    float v = -1e30f;
    if (tid < PP) v = g_coef[((size_t)(b * PP + tid)) * NCN + n];
    red[tid] = v; __syncthreads();
    for (int st = 128; st > 0; st >>= 1) {
        if (tid < st) red[tid] = fmaxf(red[tid], red[tid + st]);
        __syncthreads();
    }
    if (tid == 0) s_mx = red[0];
    __syncthreads();
    float e = 0.0f;
    if (tid < PP) e = __expf(v - s_mx);
    red[tid] = e; __syncthreads();
    for (int st = 128; st > 0; st >>= 1) {
        if (tid < st) red[tid] += red[tid + st];
        __syncthreads();
    }
    if (tid == 0) s_sum = red[0];
    __syncthreads();
    if (tid < PP)
        g_coef[((size_t)(b * PP + tid)) * NCN + n] = e / s_sum;
}

__global__ __launch_bounds__(256) void k_attn() {
    int cb = blockIdx.x * 256;
    int n0 = blockIdx.y * 16;
    int b  = blockIdx.z;
    int tid = threadIdx.x;
    __shared__ float sc[PP * 16];
    for (int i = tid; i < PP * 16; i += 256) {
        int p = i >> 4, j = i & 15;
        int n = n0 + j;
        sc[i] = (n < NCN) ? g_coef[((size_t)(b * PP + p)) * NCN + n] : 0.0f;
    }
    __syncthreads();
    float acc[16];
#pragma unroll
    for (int j = 0; j < 16; j++) acc[j] = 0.0f;
    for (int p = 0; p < PP; p++) {
        float f = g_fmap[((size_t)(b * PP + p)) * CC + cb + tid];
#pragma unroll
        for (int j = 0; j < 16; j++) acc[j] += sc[p * 16 + j] * f;
    }
#pragma unroll
    for (int j = 0; j < 16; j++) {
        int n = n0 + j;
        if (n >= NCN) break;
        size_t o = ((size_t)(b * NCN + n)) * CC + cb + tid;
        float v = acc[j];
        g_x[o] = v;
        __nv_bfloat16 h = __float2bfloat16(v);
        g_xh[o] = h;
        g_xl[o] = __float2bfloat16(v - __bfloat162float(h));
    }
}

__global__ void k_edgeidx(const float* __restrict__ Es, const float* __restrict__ Ee) {
    int e = blockIdx.x * blockDim.x + threadIdx.x;
    if (e >= NEE) return;
    int si = 0, ei = 0;
    for (int n = 0; n < NCN; n++) {
        if (Es[(size_t)e * NCN + n] > 0.5f) si = n;
        if (Ee[(size_t)e * NCN + n] > 0.5f) ei = n;
    }
    g_es[e] = si;
    g_ee[e] = ei;
}

__global__ void k_edgecsr() {
    __shared__ int see[NEE];
    __shared__ int cnt[NCN];
    __shared__ int off[NCN + 1];
    int tid = threadIdx.x;
    for (int i = tid; i < NEE; i += 256) see[i] = g_ee[i];
    for (int i = tid; i < NCN; i += 256) cnt[i] = 0;
    __syncthreads();
    for (int i = tid; i < NEE; i += 256) atomicAdd(&cnt[see[i]], 1);
    __syncthreads();
    if (tid == 0) {
        off[0] = 0;
        for (int n = 0; n < NCN; n++) off[n + 1] = off[n] + cnt[n];
    }
    __syncthreads();
    for (int e = tid; e < NEE; e += 256) {
        int n = see[e];
        int r = 0;
        for (int e2 = 0; e2 < e; e2++) r += (see[e2] == n) ? 1 : 0;
        g_elist[off[n] + r] = g_es[e];
    }
    for (int i = tid; i <= NCN; i += 256) g_eoff[i] = off[i];
}

__global__ __launch_bounds__(256) void k_edgehalf(
    const float* __restrict__ Uix, const float* __restrict__ Ujx,
    const float* __restrict__ Vix, const float* __restrict__ Vjx,
    const float* __restrict__ bu,  const float* __restrict__ bv,
    float* __restrict__ hout)
{
    int n = blockIdx.x, b = blockIdx.y;
    int tid = threadIdx.x;
    int lo = g_eoff[n], hi = g_eoff[n + 1];

    size_t base = ((size_t)(b * NCN + n)) * CC;
    float acc[8], vn[8];
#pragma unroll
    for (int j = 0; j < 8; j++) {
        int c = tid + j * 256;
        acc[j] = Uix[base + c] + bu[c];
        vn[j]  = Vix[base + c] + bv[c];
    }
    for (int idx = lo; idx < hi; idx++) {
        int se = g_elist[idx];
        size_t b2 = ((size_t)(b * NCN + se)) * CC;
#pragma unroll
        for (int j = 0; j < 8; j++) {
            int c = tid + j * 256;
            float g = sigm(vn[j] + Vjx[b2 + c]);
            acc[j] += g * Ujx[b2 + c];
        }
    }
#pragma unroll
    for (int j = 0; j < 8; j++) hout[base + tid + j * 256] = acc[j];
}

__global__ void k_bnstats(const float* __restrict__ h) {
    __shared__ float ssum[8][33];
    __shared__ float ssq [8][33];
    int tx = threadIdx.x;
    int ty = threadIdx.y;
    int c = blockIdx.x * 32 + tx;
    float s = 0.0f, sq = 0.0f;
    for (int r = ty; r < MROWS; r += 8) {
        float v = h[(size_t)r * CC + c];
        s += v; sq += v * v;
    }
    ssum[ty][tx] = s; ssq[ty][tx] = sq;
    __syncthreads();
    if (ty == 0) {
        for (int y = 1; y < 8; y++) { s += ssum[y][tx]; sq += ssq[y][tx]; }
        float m = s / (float)MROWS;
        g_mean[c] = m;
        g_var[c] = sq / (float)MROWS - m * m;
    }
}

__global__ void k_bnapply(const float* __restrict__ h,
                          const float* __restrict__ gamma, const float* __restrict__ beta,
                          const float* __restrict__ res)
{
    int idx = blockIdx.x * blockDim.x + threadIdx.x;
    if (idx >= MROWS * CC) return;
    int c = idx & (CC - 1);
    float v = (h[idx] - g_mean[c]) * rsqrtf(g_var[c] + EPSV) * gamma[c] + beta[c];
    if (res) v += res[idx];
    v = fmaxf(v, 0.0f);
    g_x[idx] = v;
    __nv_bfloat16 hh = __float2bfloat16(v);
    g_xh[idx] = hh;
    g_xl[idx] = __float2bfloat16(v - __bfloat162float(hh));
}

__global__ __launch_bounds__(256) void k_head(const float* __restrict__ fcw,
                                              const float* __restrict__ fcb,
                                              float* __restrict__ out)
{
    int bn = blockIdx.x;
    int b = bn / NCN, n = bn % NCN;
    int tid = threadIdx.x;
    __shared__ float red[256];
    const float* xr = g_x + (size_t)bn * CC;
    const float* wr = fcw + (size_t)n * CC;
    float s = 0.0f;
    for (int c = tid; c < CC; c += 256) s += xr[c] * wr[c];
    red[tid] = s; __syncthreads();
    for (int st = 128; st > 0; st >>= 1) {
        if (tid < st) red[tid] += red[tid + st];
        __syncthreads();
    }
    if (tid == 0) {
        float v = red[0] + fcb[n];
        float sg = sigm(v);
        if (n < 13) {
            out[b * 13 + n] = sg;
        } else if (n < 51) {
            out[52 + b * 38 + (n - 13)] = sg;
        } else {
            out[204 + b * 149 + (n - 51)] = v;
            out[800 + b * 149 + (n - 51)] = sg;
        }
    }
}

// ================================ launch =====================================
extern "C" void kernel_launch(void* const* d_in, const int* in_sizes, int n_in,
                              void* d_out, int out_size)
{
    const float* img  = (const float*)d_in[0];
    const float* word = (const float*)d_in[1];
    const float* Es   = (const float*)d_in[2];
    const float* Ee   = (const float*)d_in[3];
    const float* W1   = (const float*)d_in[4];
    const float* W2   = (const float*)d_in[5];
    const float* W3   = (const float*)d_in[6];
    const float* b3   = (const float*)d_in[7];
    const float* Wa   = (const float*)d_in[8];
    const float* ba   = (const float*)d_in[9];
    const float* bu1  = (const float*)d_in[19];
    const float* bv1  = (const float*)d_in[20];
    const float* bu2  = (const float*)d_in[21];
    const float* bv2  = (const float*)d_in[22];
    const float* bn1b = (const float*)d_in[23];
    const float* bn2b = (const float*)d_in[24];
    const float* bn1g = (const float*)d_in[25];
    const float* bn2g = (const float*)d_in[26];
    const float* fcw  = (const float*)d_in[27];
    const float* fcb  = (const float*)d_in[28];
    float* out = (float*)d_out;

    const float* wsrc[9] = {
        (const float*)d_in[10], (const float*)d_in[11], (const float*)d_in[12],
        (const float*)d_in[13], (const float*)d_in[18], (const float*)d_in[14],
        (const float*)d_in[15], (const float*)d_in[16], (const float*)d_in[17]
    };

    float *p_fwh, *p_fwd, *p_x, *p_h, *p_t;
    __nv_bfloat16 *p_fmh, *p_fml, *p_xh, *p_xl, *p_wh, *p_wl;
    cudaGetSymbolAddress((void**)&p_fwh,  g_fwh);
    cudaGetSymbolAddress((void**)&p_fwd,  g_fwd);
    cudaGetSymbolAddress((void**)&p_x,    g_x);
    cudaGetSymbolAddress((void**)&p_h,    g_h);
    cudaGetSymbolAddress((void**)&p_t,    g_t);
    cudaGetSymbolAddress((void**)&p_fmh,  g_fmh);
    cudaGetSymbolAddress((void**)&p_fml,  g_fml);
    cudaGetSymbolAddress((void**)&p_xh,   g_xh);
    cudaGetSymbolAddress((void**)&p_xl,   g_xl);
    cudaGetSymbolAddress((void**)&p_wh,   g_wbh);
    cudaGetSymbolAddress((void**)&p_wl,   g_wbl);

    cudaFuncSetAttribute(k_tgemm, cudaFuncAttributeMaxDynamicSharedMemorySize,
                         SMTOT);

    // 1) fmap transpose + bf16 split
    k_transpose<<<dim3((PP + 31) / 32, CC / 32, BB), dim3(32, 8)>>>(img);

    // 2) weight conversions
    {
        WP27 wp;
        for (int l = 0; l < NL; l++)
            for (int s = 0; s < 9; s++)
                wp.p[l * 9 + s] = (const float4*)(wsrc[s] + (size_t)l * WSLOT);
        k_convall<<<dim3((int)(WSLOT / 16 / 256), 27), 256>>>(wp);
    }
    k_conv<<<(INTD * CC / 8 + 255) / 256, 256>>>(
        (const float4*)W1, p_wh + W1OFF, p_wl + W1OFF, INTD * CC / 4);

    // 3) f_wh via split-K=4 (ntilesPerW = INTD/TN = 4)
    k_tgemm<<<dim3(INTD / TN, (BP + TM - 1) / TM, 4), 256, SMTOT>>>(
        p_fmh, p_fml, p_wh + W1OFF, p_wl + W1OFF, p_t,
        BP, CC, INTD, INTD / TN, CC / TK / 4, (size_t)BP * INTD);
    k_red4<<<(BP * INTD / 4 + 255) / 256, 256>>>();

    // 4) f_wd
    k_sgemm<<<dim3((INTD + 63) / 64, (NCN + 63) / 64), 256>>>(word, W2, p_fwd,
                                                              NCN, INTD, WDD);
    // 5) collapsed attention weights
    k_weff1<<<dim3(INTD / 256, 16), 256>>>(W3, Wa);
    k_weff2<<<INTD / 256, 256>>>();
    k_ceff<<<1, 256>>>(Wa, b3, ba);

    // 6) attention
    k_coef<<<BP, 256>>>();
    k_softmax<<<dim3(NCN, BB), 256>>>();
    k_attn<<<dim3(CC / 256, (NCN + 15) / 16, BB), 256>>>();

    // 7) edges
    k_edgeidx<<<(NEE + 255) / 256, 256>>>(Es, Ee);
    k_edgecsr<<<1, 256>>>();

    const int nelem = MROWS * CC;
    const int mtiles = (MROWS + TM - 1) / TM;   // 7
    const int ntiles = CC / TN;                 // 8

    for (int l = 0; l < NL; l++) {
        size_t sb = (size_t)l * 9;
        size_t bo = (size_t)l * CC;

        k_tgemm<<<dim3(5 * ntiles, mtiles, 1), 256, SMTOT>>>(
            p_xh, p_xl, p_wh + sb * WSLOT, p_wl + sb * WSLOT,
            p_t, MROWS, CC, CC, ntiles, CC / TK, 0);
        k_edgehalf<<<dim3(NCN, BB), 256>>>(p_t, p_t + XSLOT, p_t + 2 * XSLOT,
                                           p_t + 3 * XSLOT, bu1 + bo, bv1 + bo, p_h);
        k_bnstats<<<CC / 32, dim3(32, 8)>>>(p_h);
        k_bnapply<<<(nelem + 255) / 256, 256>>>(p_h, bn1g + bo, bn1b + bo, nullptr);

        k_tgemm<<<dim3(4 * ntiles, mtiles, 1), 256, SMTOT>>>(
            p_xh, p_xl, p_wh + (sb + 5) * WSLOT, p_wl + (sb + 5) * WSLOT,
            p_t, MROWS, CC, CC, ntiles, CC / TK, 0);
        k_edgehalf<<<dim3(NCN, BB), 256>>>(p_t, p_t + XSLOT, p_t + 2 * XSLOT,
                                           p_t + 3 * XSLOT, bu2 + bo, bv2 + bo, p_h);
        k_bnstats<<<CC / 32, dim3(32, 8)>>>(p_h);
        k_bnapply<<<(nelem + 255) / 256, 256>>>(p_h, bn2g + bo, bn2b + bo,
                                                p_t + 4 * XSLOT);
    }

    k_head<<<BB * NCN, 256>>>(fcw, fcb, out);
}

// round 16
// speedup vs baseline: 1.1643x; 1.1643x over previous
#include <cuda_runtime.h>
#include <cuda_bf16.h>
#include <math.h>
#include <stdint.h>

#define BB   4
#define CC   2048
#define PP   196
#define BP   784
#define NCN  200
#define WDD  300
#define INTD 1024
#define NEE  800
#define NL   3
#define EPSV 1e-5f

#define MROWS (BB*NCN)               // 800
#define WSLOT ((size_t)CC*CC)
#define XSLOT ((size_t)MROWS*CC)
#define W1OFF ((size_t)27*WSLOT)

// ---------------- scratch ----------------
__device__ float g_fmap[BP * CC];
__device__ __nv_bfloat16 g_fmh[BP * CC];
__device__ __nv_bfloat16 g_fml[BP * CC];
__device__ float g_fwh [BP * INTD];
__device__ float g_fwd [NCN * INTD];
__device__ float g_wpart[16 * INTD];
__device__ float g_weff[INTD];
__device__ float g_ceff[1];
__device__ float g_coef[BP * NCN];
__device__ __nv_bfloat16 g_xh[XSLOT];
__device__ __nv_bfloat16 g_xl[XSLOT];
__device__ float g_h   [XSLOT];
__device__ float g_t   [5 * XSLOT];
__device__ float g_mean[CC];
__device__ float g_var [CC];
__device__ int   g_es  [NEE];
__device__ int   g_ee  [NEE];
__device__ int   g_eoff[NCN + 1];
__device__ int   g_elist[NEE];
__device__ __nv_bfloat16 g_wbh[27 * WSLOT + (size_t)INTD * CC];
__device__ __nv_bfloat16 g_wbl[27 * WSLOT + (size_t)INTD * CC];

__device__ __forceinline__ float sigm(float x) {
    return 1.0f / (1.0f + __expf(-x));
}

// fma-pipe sigmoid: Schraudolph-style exact-split exp2 + Newton rcp.
__device__ __forceinline__ float fast_sigm(float x) {
    float t = fminf(fmaxf(x, -30.0f), 30.0f);
    float z = -t * 1.4426950408889634f;            // -x * log2(e)
    float zr = z + 12582912.0f;
    int   j  = __float_as_int(zr) - 0x4B400000;
    float f  = z - (zr - 12582912.0f);
    float p = 0.0096181291f;
    p = fmaf(p, f, 0.0555041087f);
    p = fmaf(p, f, 0.2402265069f);
    p = fmaf(p, f, 0.6931471806f);
    p = fmaf(p, f, 1.0f);
    float s = __int_as_float((j + 127) << 23);
    float e = p * s;                                // = exp(-x)
    float u = e + 1.0f;
    float r = __int_as_float(0x7EF311C3 - __float_as_int(u));
    r = r * fmaf(-u, r, 2.0f);
    r = r * fmaf(-u, r, 2.0f);
    return r;
}

__device__ __forceinline__ float fast_tanh(float x) {
    float t = fminf(fmaxf(x, -8.0f), 8.0f);
    float z = t * 2.8853900817779268f;
    float zr = z + 12582912.0f;
    int   j  = __float_as_int(zr) - 0x4B400000;
    float f  = z - (zr - 12582912.0f);
    float p = 0.0096181291f;
    p = fmaf(p, f, 0.0555041087f);
    p = fmaf(p, f, 0.2402265069f);
    p = fmaf(p, f, 0.6931471806f);
    p = fmaf(p, f, 1.0f);
    float s = __int_as_float((j + 127) << 23);
    float e = p * s;
    float u = e + 1.0f;
    float r = __int_as_float(0x7EF311C3 - __float_as_int(u));
    r = r * fmaf(-u, r, 2.0f);
    r = r * fmaf(-u, r, 2.0f);
    return (e - 1.0f) * r;
}

__device__ __forceinline__ uint32_t smem_u32(const void* p) {
    uint32_t a;
    asm("{ .reg .u64 t; cvta.to.shared.u64 t, %1; cvt.u32.u64 %0, t; }"
        : "=r"(a) : "l"(p));
    return a;
}

#define LDSM4(R, addr) \
    asm volatile("ldmatrix.sync.aligned.m8n8.x4.shared.b16 {%0,%1,%2,%3}, [%4];" \
        : "=r"((R)[0]), "=r"((R)[1]), "=r"((R)[2]), "=r"((R)[3]) : "r"(addr))

#define MMA16816(C, A, B0, B1) \
    asm volatile("mma.sync.aligned.m16n8k16.row.col.f32.bf16.bf16.f32 " \
        "{%0,%1,%2,%3},{%4,%5,%6,%7},{%8,%9},{%0,%1,%2,%3};" \
        : "+f"((C)[0]), "+f"((C)[1]), "+f"((C)[2]), "+f"((C)[3]) \
        : "r"((A)[0]), "r"((A)[1]), "r"((A)[2]), "r"((A)[3]), "r"(B0), "r"(B1))

#define CP_ASYNC16(dst, src, vld) \
    asm volatile("cp.async.cg.shared.global [%0], [%1], 16, %2;" \
        :: "r"(dst), "l"(src), "r"(vld))
#define CP_COMMIT() asm volatile("cp.async.commit_group;" ::: "memory")
#define CP_WAIT1()  asm volatile("cp.async.wait_group 1;" ::: "memory")
#define CP_WAIT0()  asm volatile("cp.async.wait_group 0;" ::: "memory")

// ============================ HMMA GEMM (frozen champion) ====================
// 128x128 tile, 8 warps (2x4) of 64x32, XOR-swizzled 64B rows,
// 3-stage cp.async, ONE barrier per chunk, 2 CTAs/SM.
#define TM 128
#define TN 128
#define TK 32
#define MATSZ  (128 * 64)
#define STAGE  (4 * MATSZ)             // 32768
#define NSTG   3
#define SMTOT  (NSTG * STAGE)          // 98304

__device__ __forceinline__ uint32_t swz_off(int row, int g) {
    return (uint32_t)(row * 64 + ((g ^ ((row >> 1) & 3)) << 4));
}

__global__ void __launch_bounds__(256, 2) k_tgemm(
    const __nv_bfloat16* __restrict__ Ah, const __nv_bfloat16* __restrict__ Al,
    const __nv_bfloat16* __restrict__ Wh, const __nv_bfloat16* __restrict__ Wl,
    float* __restrict__ out, int M, int K, int nPerW, int ntilesPerW,
    int nchPerZ, size_t zStride)
{
    extern __shared__ char smem[];
    const uint32_t sbase = smem_u32(smem);
    const int tid  = threadIdx.x;
    const int lane = tid & 31, wid = tid >> 5;
    const int wm = wid >> 2, wn = wid & 3;
    const int widx = blockIdx.x / ntilesPerW;
    const int nt   = blockIdx.x % ntilesPerW;
    const int bm   = blockIdx.y * TM;
    const int kb0  = blockIdx.z * nchPerZ * TK;
    const __nv_bfloat16* Wbh = Wh + (size_t)widx * nPerW * K + (size_t)nt * TN * K;
    const __nv_bfloat16* Wbl = Wl + (size_t)widx * nPerW * K + (size_t)nt * TN * K;
    float* outp = out + (size_t)blockIdx.z * zStride
                      + (size_t)widx * M * nPerW + (size_t)nt * TN;

    float acc[4][4][4];
#pragma unroll
    for (int a = 0; a < 4; a++)
#pragma unroll
        for (int b = 0; b < 4; b++)
#pragma unroll
            for (int c = 0; c < 4; c++) acc[a][b][c] = 0.0f;

    auto load_stage = [&](int ch, int st) {
        const uint32_t so = sbase + st * STAGE;
        const int kb = kb0 + ch * TK;
#pragma unroll
        for (int it = 0; it < 8; it++) {
            int idx = tid + it * 256;
            int mat = idx >> 9;
            int r   = (idx >> 2) & 127;
            int q   = idx & 3;
            const __nv_bfloat16* src;
            int vld = 16;
            if (mat < 2) {
                int gr = bm + r;
                if (gr >= M) { vld = 0; gr = M - 1; }
                src = (mat ? Al : Ah) + (size_t)gr * K + kb + q * 8;
            } else {
                src = (mat == 3 ? Wbl : Wbh) + (size_t)r * K + kb + q * 8;
            }
            uint32_t dst = so + mat * MATSZ + swz_off(r, q);
            CP_ASYNC16(dst, src, vld);
        }
        CP_COMMIT();
    };

    const int a_row0 = wm * 64 + (lane & 15);
    const int a_g    = lane >> 4;
    const int b_row0 = wn * 32 + (lane & 7) + ((lane & 16) ? 8 : 0);
    const int b_g    = (lane & 8) ? 1 : 0;

    auto compute_stage = [&](int st) {
        const uint32_t so = sbase + st * STAGE;
#pragma unroll
        for (int ks = 0; ks < 2; ks++) {
            uint32_t bh[2][4], bl[2][4];
#pragma unroll
            for (int p = 0; p < 2; p++) {
                int row = b_row0 + p * 16;
                uint32_t bd = so + 2 * MATSZ + swz_off(row, ks * 2 + b_g);
                LDSM4(bh[p], bd);
                LDSM4(bl[p], bd + MATSZ);
            }
#pragma unroll
            for (int im = 0; im < 4; im++) {
                int row = a_row0 + im * 16;
                uint32_t ad = so + swz_off(row, ks * 2 + a_g);
                uint32_t ah[4], al[4];
                LDSM4(ah, ad);
                LDSM4(al, ad + MATSZ);
#pragma unroll
                for (int in = 0; in < 4; in++) {
                    int p = in >> 1, s2 = (in & 1) * 2;
                    MMA16816(acc[im][in], ah, bh[p][s2], bh[p][s2 + 1]);
                    MMA16816(acc[im][in], ah, bl[p][s2], bl[p][s2 + 1]);
                    MMA16816(acc[im][in], al, bh[p][s2], bh[p][s2 + 1]);
                }
            }
        }
    };

    const int nch = nchPerZ;
    load_stage(0, 0);
    if (nch > 1) load_stage(1, 1);
    for (int ch = 0; ch < nch; ch++) {
        if (ch + 1 < nch) { CP_WAIT1(); } else { CP_WAIT0(); }
        __syncthreads();
        if (ch + 2 < nch) load_stage(ch + 2, (ch + 2) % NSTG);
        compute_stage(ch % NSTG);
    }

#pragma unroll
    for (int im = 0; im < 4; im++) {
        int r0 = bm + wm * 64 + im * 16 + (lane >> 2);
#pragma unroll
        for (int in = 0; in < 4; in++) {
            int col = wn * 32 + (in >> 1) * 16 + (in & 1) * 8 + (lane & 3) * 2;
            if (r0 < M) {
                float2 v; v.x = acc[im][in][0]; v.y = acc[im][in][1];
                *reinterpret_cast<float2*>(outp + (size_t)r0 * nPerW + col) = v;
            }
            if (r0 + 8 < M) {
                float2 v; v.x = acc[im][in][2]; v.y = acc[im][in][3];
                *reinterpret_cast<float2*>(outp + (size_t)(r0 + 8) * nPerW + col) = v;
            }
        }
    }
}

// split-K reduce for W1
__global__ void k_red4() {
    int i = blockIdx.x * 256 + threadIdx.x;
    const int S4 = BP * INTD / 4;
    if (i >= S4) return;
    const float4* t = reinterpret_cast<const float4*>(g_t);
    float4 a = t[i], b = t[S4 + i], c = t[2 * S4 + i], d = t[3 * S4 + i];
    float4 r;
    r.x = (a.x + b.x) + (c.x + d.x);
    r.y = (a.y + b.y) + (c.y + d.y);
    r.z = (a.z + b.z) + (c.z + d.z);
    r.w = (a.w + b.w) + (c.w + d.w);
    reinterpret_cast<float4*>(g_fwh)[i] = r;
}

// ============================ small kernels ==================================

struct WP27 { const float4* p[27]; };

__device__ __forceinline__ void split4(float4 v, uint2& h2, uint2& l2) {
    __nv_bfloat16 hx = __float2bfloat16(v.x);
    __nv_bfloat16 hy = __float2bfloat16(v.y);
    __nv_bfloat16 hz = __float2bfloat16(v.z);
    __nv_bfloat16 hw = __float2bfloat16(v.w);
    __nv_bfloat162 a = __halves2bfloat162(hx, hy);
    __nv_bfloat162 b = __halves2bfloat162(hz, hw);
    h2.x = *reinterpret_cast<uint32_t*>(&a);
    h2.y = *reinterpret_cast<uint32_t*>(&b);
    __nv_bfloat162 c = __halves2bfloat162(
        __float2bfloat16(v.x - __bfloat162float(hx)),
        __float2bfloat16(v.y - __bfloat162float(hy)));
    __nv_bfloat162 d = __halves2bfloat162(
        __float2bfloat16(v.z - __bfloat162float(hz)),
        __float2bfloat16(v.w - __bfloat162float(hw)));
    l2.x = *reinterpret_cast<uint32_t*>(&c);
    l2.y = *reinterpret_cast<uint32_t*>(&d);
}

__global__ void k_convall(WP27 w) {
    int slot = blockIdx.y;
    size_t i = ((size_t)blockIdx.x * 256 + threadIdx.x) * 4;
    const float4* src = w.p[slot];
    float4 v0 = __ldcs(src + i);
    float4 v1 = __ldcs(src + i + 1);
    float4 v2 = __ldcs(src + i + 2);
    float4 v3 = __ldcs(src + i + 3);
    uint4 ho0, lo0, ho1, lo1;
    uint2 h2, l2;
    split4(v0, h2, l2); ho0.x = h2.x; ho0.y = h2.y; lo0.x = l2.x; lo0.y = l2.y;
    split4(v1, h2, l2); ho0.z = h2.x; ho0.w = h2.y; lo0.z = l2.x; lo0.w = l2.y;
    split4(v2, h2, l2); ho1.x = h2.x; ho1.y = h2.y; lo1.x = l2.x; lo1.y = l2.y;
    split4(v3, h2, l2); ho1.z = h2.x; ho1.w = h2.y; lo1.z = l2.x; lo1.w = l2.y;
    size_t base = (size_t)slot * WSLOT / 8 + i / 2;
    __stcs(reinterpret_cast<uint4*>(g_wbh) + base,     ho0);
    __stcs(reinterpret_cast<uint4*>(g_wbh) + base + 1, ho1);
    __stcs(reinterpret_cast<uint4*>(g_wbl) + base,     lo0);
    __stcs(reinterpret_cast<uint4*>(g_wbl) + base + 1, lo1);
}

__global__ void k_conv(const float4* __restrict__ src,
                       __nv_bfloat16* __restrict__ dh,
                       __nv_bfloat16* __restrict__ dl, int n4)
{
    int i = (blockIdx.x * blockDim.x + threadIdx.x) * 2;
    if (i >= n4) return;
    float4 v0 = __ldcs(src + i);
    float4 v1 = __ldcs(src + i + 1);
    uint4 ho, lo;
    uint2 h2, l2;
    split4(v0, h2, l2); ho.x = h2.x; ho.y = h2.y; lo.x = l2.x; lo.y = l2.y;
    split4(v1, h2, l2); ho.z = h2.x; ho.w = h2.y; lo.z = l2.x; lo.w = l2.y;
    __stcs(reinterpret_cast<uint4*>(dh) + i / 2, ho);
    __stcs(reinterpret_cast<uint4*>(dl) + i / 2, lo);
}

__global__ void k_transpose(const float* __restrict__ img) {
    __shared__ float tile[32][33];
    int b  = blockIdx.z;
    int p0 = blockIdx.x * 32;
    int c0 = blockIdx.y * 32;
    int tx = threadIdx.x, ty = threadIdx.y;
#pragma unroll
    for (int j = 0; j < 4; j++) {
        int c = c0 + ty + j * 8;
        int p = p0 + tx;
        float v = (p < PP) ? img[((size_t)b * CC + c) * PP + p] : 0.0f;
        tile[ty + j * 8][tx] = v;
    }
    __syncthreads();
#pragma unroll
    for (int j = 0; j < 4; j++) {
        int p = p0 + ty + j * 8;
        int c = c0 + tx;
        if (p < PP) {
            float v = tile[tx][ty + j * 8];
            size_t o = ((size_t)b * PP + p) * CC + c;
            g_fmap[o] = v;
            __nv_bfloat16 h = __float2bfloat16(v);
            g_fmh[o] = h;
            g_fml[o] = __float2bfloat16(v - __bfloat162float(h));
        }
    }
}

__global__ __launch_bounds__(256) void k_sgemm(
    const float* __restrict__ A, const float* __restrict__ W,
    float* __restrict__ C, int M, int N, int K)
{
    __shared__ float As[16][65];
    __shared__ float Bs[16][65];
    const int tid = threadIdx.x;
    const int tx = tid & 15, ty = tid >> 4;
    const int bm = blockIdx.y * 64, bn = blockIdx.x * 64;
    const int lr = tid >> 2;
    const int lk = (tid & 3) << 2;

    float acc[4][4];
#pragma unroll
    for (int i = 0; i < 4; i++)
#pragma unroll
        for (int j = 0; j < 4; j++) acc[i][j] = 0.0f;

    for (int k0 = 0; k0 < K; k0 += 16) {
        float a0 = 0, a1 = 0, a2 = 0, a3 = 0;
        int arow = bm + lr;
        if (arow < M) {
            const float* ap = A + (size_t)arow * K + k0 + lk;
            if (k0 + lk + 0 < K) a0 = ap[0];
            if (k0 + lk + 1 < K) a1 = ap[1];
            if (k0 + lk + 2 < K) a2 = ap[2];
            if (k0 + lk + 3 < K) a3 = ap[3];
        }
        As[lk + 0][lr] = a0; As[lk + 1][lr] = a1;
        As[lk + 2][lr] = a2; As[lk + 3][lr] = a3;

        float b0 = 0, b1 = 0, b2 = 0, b3 = 0;
        int wrow = bn + lr;
        if (wrow < N) {
            const float* wp = W + (size_t)wrow * K + k0 + lk;
            if (k0 + lk + 0 < K) b0 = wp[0];
            if (k0 + lk + 1 < K) b1 = wp[1];
            if (k0 + lk + 2 < K) b2 = wp[2];
            if (k0 + lk + 3 < K) b3 = wp[3];
        }
        Bs[lk + 0][lr] = b0; Bs[lk + 1][lr] = b1;
        Bs[lk + 2][lr] = b2; Bs[lk + 3][lr] = b3;

        __syncthreads();
#pragma unroll
        for (int k = 0; k < 16; k++) {
            float av[4], bv[4];
#pragma unroll
            for (int i = 0; i < 4; i++) av[i] = As[k][ty * 4 + i];
#pragma unroll
            for (int j = 0; j < 4; j++) bv[j] = Bs[k][tx * 4 + j];
#pragma unroll
            for (int i = 0; i < 4; i++)
#pragma unroll
                for (int j = 0; j < 4; j++) acc[i][j] += av[i] * bv[j];
        }
        __syncthreads();
    }
#pragma unroll
    for (int i = 0; i < 4; i++) {
        int r = bm + ty * 4 + i;
        if (r >= M) continue;
#pragma unroll
        for (int j = 0; j < 4; j++) {
            int cI = bn + tx * 4 + j;
            if (cI < N) C[(size_t)r * N + cI] = acc[i][j];
        }
    }
}

__global__ void k_weff1(const float* __restrict__ W3, const float* __restrict__ Wa) {
    int i = blockIdx.x * 256 + threadIdx.x;
    int oc = blockIdx.y;
    float s = 0.0f;
    for (int o = oc * 64; o < (oc + 1) * 64; o++)
        s += Wa[o] * W3[(size_t)o * INTD + i];
    g_wpart[oc * INTD + i] = s;
}
__global__ void k_weff2() {
    int i = blockIdx.x * 256 + threadIdx.x;
    float s = 0.0f;
#pragma unroll
    for (int oc = 0; oc < 16; oc++) s += g_wpart[oc * INTD + i];
    g_weff[i] = s;
}

__global__ void k_ceff(const float* __restrict__ Wa, const float* __restrict__ b3,
                       const float* __restrict__ ba) {
    __shared__ float red[256];
    int tid = threadIdx.x;
    float s = 0.0f;
    for (int i = tid; i < INTD; i += 256) s += Wa[i] * b3[i];
    red[tid] = s; __syncthreads();
    for (int st = 128; st > 0; st >>= 1) {
        if (tid < st) red[tid] += red[tid + st];
        __syncthreads();
    }
    if (tid == 0) g_ceff[0] = red[0] + ba[0];
}

__global__ __launch_bounds__(256) void k_coef() {
    int bp = blockIdx.x;
    int tid = threadIdx.x;
    __shared__ float s_fwh[INTD];
    __shared__ float s_wef[INTD];
    for (int i = tid; i < INTD; i += 256) {
        s_fwh[i] = g_fwh[(size_t)bp * INTD + i];
        s_wef[i] = g_weff[i];
    }
    __syncthreads();
    int warp = tid >> 5, lane = tid & 31;
    float ce = g_ceff[0];
    for (int n = warp; n < NCN; n += 8) {
        const float* fw = g_fwd + (size_t)n * INTD;
        float acc = 0.0f;
        for (int i = lane; i < INTD; i += 32)
            acc += fast_tanh(s_fwh[i] * fw[i]) * s_wef[i];
#pragma unroll
        for (int off = 16; off > 0; off >>= 1)
            acc += __shfl_down_sync(0xffffffffu, acc, off);
        if (lane == 0) g_coef[(size_t)bp * NCN + n] = acc + ce;
    }
}

__global__ __launch_bounds__(256) void k_softmax() {
    int n = blockIdx.x, b = blockIdx.y;
    int tid = threadIdx.x;
    __shared__ float red[256];
    __shared__ float s_mx, s_sum;
    float v = -1e30f;
    if (tid < PP) v = g_coef[((size_t)(b * PP + tid)) * NCN + n];
    red[tid] = v; __syncthreads();
    for (int st = 128; st > 0; st >>= 1) {
        if (tid < st) red[tid] = fmaxf(red[tid], red[tid + st]);
        __syncthreads();
    }
    if (tid == 0) s_mx = red[0];
    __syncthreads();
    float e = 0.0f;
    if (tid < PP) e = __expf(v - s_mx);
    red[tid] = e; __syncthreads();
    for (int st = 128; st > 0; st >>= 1) {
        if (tid < st) red[tid] += red[tid + st];
        __syncthreads();
    }
    if (tid == 0) s_sum = red[0];
    __syncthreads();
    if (tid < PP)
        g_coef[((size_t)(b * PP + tid)) * NCN + n] = e / s_sum;
}

// x -> bf16 hi/lo only (fp32 copy eliminated; head reconstructs hi+lo)
__global__ __launch_bounds__(256) void k_attn() {
    int cb = blockIdx.x * 256;
    int n0 = blockIdx.y * 16;
    int b  = blockIdx.z;
    int tid = threadIdx.x;
    __shared__ float sc[PP * 16];
    for (int i = tid; i < PP * 16; i += 256) {
        int p = i >> 4, j = i & 15;
        int n = n0 + j;
        sc[i] = (n < NCN) ? g_coef[((size_t)(b * PP + p)) * NCN + n] : 0.0f;
    }
    __syncthreads();
    float acc[16];
#pragma unroll
    for (int j = 0; j < 16; j++) acc[j] = 0.0f;
    for (int p = 0; p < PP; p++) {
        float f = g_fmap[((size_t)(b * PP + p)) * CC + cb + tid];
#pragma unroll
        for (int j = 0; j < 16; j++) acc[j] += sc[p * 16 + j] * f;
    }
#pragma unroll
    for (int j = 0; j < 16; j++) {
        int n = n0 + j;
        if (n >= NCN) break;
        size_t o = ((size_t)(b * NCN + n)) * CC + cb + tid;
        float v = acc[j];
        __nv_bfloat16 h = __float2bfloat16(v);
        g_xh[o] = h;
        g_xl[o] = __float2bfloat16(v - __bfloat162float(h));
    }
}

__global__ void k_edgeidx(const float* __restrict__ Es, const float* __restrict__ Ee) {
    int e = blockIdx.x * blockDim.x + threadIdx.x;
    if (e >= NEE) return;
    int si = 0, ei = 0;
    for (int n = 0; n < NCN; n++) {
        if (Es[(size_t)e * NCN + n] > 0.5f) si = n;
        if (Ee[(size_t)e * NCN + n] > 0.5f) ei = n;
    }
    g_es[e] = si;
    g_ee[e] = ei;
}

__global__ void k_edgecsr() {
    __shared__ int see[NEE];
    __shared__ int cnt[NCN];
    __shared__ int off[NCN + 1];
    int tid = threadIdx.x;
    for (int i = tid; i < NEE; i += 256) see[i] = g_ee[i];
    for (int i = tid; i < NCN; i += 256) cnt[i] = 0;
    __syncthreads();
    for (int i = tid; i < NEE; i += 256) atomicAdd(&cnt[see[i]], 1);
    __syncthreads();
    if (tid == 0) {
        off[0] = 0;
        for (int n = 0; n < NCN; n++) off[n + 1] = off[n] + cnt[n];
    }
    __syncthreads();
    for (int e = tid; e < NEE; e += 256) {
        int n = see[e];
        int r = 0;
        for (int e2 = 0; e2 < e; e2++) r += (see[e2] == n) ? 1 : 0;
        g_elist[off[n] + r] = g_es[e];
    }
    for (int i = tid; i <= NCN; i += 256) g_eoff[i] = off[i];
}

__global__ __launch_bounds__(256) void k_edgehalf(
    const float* __restrict__ Uix, const float* __restrict__ Ujx,
    const float* __restrict__ Vix, const float* __restrict__ Vjx,
    const float* __restrict__ bu,  const float* __restrict__ bv,
    float* __restrict__ hout)
{
    int n = blockIdx.x, b = blockIdx.y;
    int tid = threadIdx.x;
    int lo = g_eoff[n], hi = g_eoff[n + 1];

    size_t base = ((size_t)(b * NCN + n)) * CC;
    float acc[8], vn[8];
#pragma unroll
    for (int j = 0; j < 8; j++) {
        int c = tid + j * 256;
        acc[j] = Uix[base + c] + bu[c];
        vn[j]  = Vix[base + c] + bv[c];
    }
    for (int idx = lo; idx < hi; idx++) {
        int se = g_elist[idx];
        size_t b2 = ((size_t)(b * NCN + se)) * CC;
#pragma unroll
        for (int j = 0; j < 8; j++) {
            int c = tid + j * 256;
            float g = fast_sigm(vn[j] + Vjx[b2 + c]);
            acc[j] += g * Ujx[b2 + c];
        }
    }
#pragma unroll
    for (int j = 0; j < 8; j++) hout[base + tid + j * 256] = acc[j];
}

__global__ void k_bnstats(const float* __restrict__ h) {
    __shared__ float ssum[8][33];
    __shared__ float ssq [8][33];
    int tx = threadIdx.x;
    int ty = threadIdx.y;
    int c = blockIdx.x * 32 + tx;
    float s = 0.0f, sq = 0.0f;
    for (int r = ty; r < MROWS; r += 8) {
        float v = h[(size_t)r * CC + c];
        s += v; sq += v * v;
    }
    ssum[ty][tx] = s; ssq[ty][tx] = sq;
    __syncthreads();
    if (ty == 0) {
        for (int y = 1; y < 8; y++) { s += ssum[y][tx]; sq += ssq[y][tx]; }
        float m = s / (float)MROWS;
        g_mean[c] = m;
        g_var[c] = sq / (float)MROWS - m * m;
    }
}

// bn apply (+residual) + relu -> bf16 hi/lo only
__global__ void k_bnapply(const float* __restrict__ h,
                          const float* __restrict__ gamma, const float* __restrict__ beta,
                          const float* __restrict__ res)
{
    int idx = blockIdx.x * blockDim.x + threadIdx.x;
    if (idx >= MROWS * CC) return;
    int c = idx & (CC - 1);
    float v = (h[idx] - g_mean[c]) * rsqrtf(g_var[c] + EPSV) * gamma[c] + beta[c];
    if (res) v += res[idx];
    v = fmaxf(v, 0.0f);
    __nv_bfloat16 hh = __float2bfloat16(v);
    g_xh[idx] = hh;
    g_xl[idx] = __float2bfloat16(v - __bfloat162float(hh));
}

// head: reconstruct x = hi + lo
__global__ __launch_bounds__(256) void k_head(const float* __restrict__ fcw,
                                              const float* __restrict__ fcb,
                                              float* __restrict__ out)
{
    int bn = blockIdx.x;
    int b = bn / NCN, n = bn % NCN;
    int tid = threadIdx.x;
    __shared__ float red[256];
    const __nv_bfloat16* xh = g_xh + (size_t)bn * CC;
    const __nv_bfloat16* xl = g_xl + (size_t)bn * CC;
    const float* wr = fcw + (size_t)n * CC;
    float s = 0.0f;
    for (int c = tid; c < CC; c += 256) {
        float x = __bfloat162float(xh[c]) + __bfloat162float(xl[c]);
        s += x * wr[c];
    }
    red[tid] = s; __syncthreads();
    for (int st = 128; st > 0; st >>= 1) {
        if (tid < st) red[tid] += red[tid + st];
        __syncthreads();
    }
    if (tid == 0) {
        float v = red[0] + fcb[n];
        float sg = sigm(v);
        if (n < 13) {
            out[b * 13 + n] = sg;
        } else if (n < 51) {
            out[52 + b * 38 + (n - 13)] = sg;
        } else {
            out[204 + b * 149 + (n - 51)] = v;
            out[800 + b * 149 + (n - 51)] = sg;
        }
    }
}

// ================================ launch =====================================
extern "C" void kernel_launch(void* const* d_in, const int* in_sizes, int n_in,
                              void* d_out, int out_size)
{
    const float* img  = (const float*)d_in[0];
    const float* word = (const float*)d_in[1];
    const float* Es   = (const float*)d_in[2];
    const float* Ee   = (const float*)d_in[3];
    const float* W1   = (const float*)d_in[4];
    const float* W2   = (const float*)d_in[5];
    const float* W3   = (const float*)d_in[6];
    const float* b3   = (const float*)d_in[7];
    const float* Wa   = (const float*)d_in[8];
    const float* ba   = (const float*)d_in[9];
    const float* bu1  = (const float*)d_in[19];
    const float* bv1  = (const float*)d_in[20];
    const float* bu2  = (const float*)d_in[21];
    const float* bv2  = (const float*)d_in[22];
    const float* bn1b = (const float*)d_in[23];
    const float* bn2b = (const float*)d_in[24];
    const float* bn1g = (const float*)d_in[25];
    const float* bn2g = (const float*)d_in[26];
    const float* fcw  = (const float*)d_in[27];
    const float* fcb  = (const float*)d_in[28];
    float* out = (float*)d_out;

    const float* wsrc[9] = {
        (const float*)d_in[10], (const float*)d_in[11], (const float*)d_in[12],
        (const float*)d_in[13], (const float*)d_in[18], (const float*)d_in[14],
        (const float*)d_in[15], (const float*)d_in[16], (const float*)d_in[17]
    };

    float *p_fwh, *p_fwd, *p_h, *p_t;
    __nv_bfloat16 *p_fmh, *p_fml, *p_xh, *p_xl, *p_wh, *p_wl;
    cudaGetSymbolAddress((void**)&p_fwh,  g_fwh);
    cudaGetSymbolAddress((void**)&p_fwd,  g_fwd);
    cudaGetSymbolAddress((void**)&p_h,    g_h);
    cudaGetSymbolAddress((void**)&p_t,    g_t);
    cudaGetSymbolAddress((void**)&p_fmh,  g_fmh);
    cudaGetSymbolAddress((void**)&p_fml,  g_fml);
    cudaGetSymbolAddress((void**)&p_xh,   g_xh);
    cudaGetSymbolAddress((void**)&p_xl,   g_xl);
    cudaGetSymbolAddress((void**)&p_wh,   g_wbh);
    cudaGetSymbolAddress((void**)&p_wl,   g_wbl);

    cudaFuncSetAttribute(k_tgemm, cudaFuncAttributeMaxDynamicSharedMemorySize,
                         SMTOT);

    // 1) fmap transpose + bf16 split
    k_transpose<<<dim3((PP + 31) / 32, CC / 32, BB), dim3(32, 8)>>>(img);

    // 2) weight conversions
    {
        WP27 wp;
        for (int l = 0; l < NL; l++)
            for (int s = 0; s < 9; s++)
                wp.p[l * 9 + s] = (const float4*)(wsrc[s] + (size_t)l * WSLOT);
        k_convall<<<dim3((int)(WSLOT / 16 / 256), 27), 256>>>(wp);
    }
    k_conv<<<(INTD * CC / 8 + 255) / 256, 256>>>(
        (const float4*)W1, p_wh + W1OFF, p_wl + W1OFF, INTD * CC / 4);

    // 3) f_wh via split-K=4
    k_tgemm<<<dim3(INTD / TN, (BP + TM - 1) / TM, 4), 256, SMTOT>>>(
        p_fmh, p_fml, p_wh + W1OFF, p_wl + W1OFF, p_t,
        BP, CC, INTD, INTD / TN, CC / TK / 4, (size_t)BP * INTD);
    k_red4<<<(BP * INTD / 4 + 255) / 256, 256>>>();

    // 4) f_wd
    k_sgemm<<<dim3((INTD + 63) / 64, (NCN + 63) / 64), 256>>>(word, W2, p_fwd,
                                                              NCN, INTD, WDD);
    // 5) collapsed attention weights
    k_weff1<<<dim3(INTD / 256, 16), 256>>>(W3, Wa);
    k_weff2<<<INTD / 256, 256>>>();
    k_ceff<<<1, 256>>>(Wa, b3, ba);

    // 6) attention
    k_coef<<<BP, 256>>>();
    k_softmax<<<dim3(NCN, BB), 256>>>();
    k_attn<<<dim3(CC / 256, (NCN + 15) / 16, BB), 256>>>();

    // 7) edges
    k_edgeidx<<<(NEE + 255) / 256, 256>>>(Es, Ee);
    k_edgecsr<<<1, 256>>>();

    const int nelem = MROWS * CC;
    const int mtiles = (MROWS + TM - 1) / TM;   // 7
    const int ntiles = CC / TN;                 // 16

    for (int l = 0; l < NL; l++) {
        size_t sb = (size_t)l * 9;
        size_t bo = (size_t)l * CC;

        k_tgemm<<<dim3(5 * ntiles, mtiles, 1), 256, SMTOT>>>(
            p_xh, p_xl, p_wh + sb * WSLOT, p_wl + sb * WSLOT,
            p_t, MROWS, CC, CC, ntiles, CC / TK, 0);
        k_edgehalf<<<dim3(NCN, BB), 256>>>(p_t, p_t + XSLOT, p_t + 2 * XSLOT,
                                           p_t + 3 * XSLOT, bu1 + bo, bv1 + bo, p_h);
        k_bnstats<<<CC / 32, dim3(32, 8)>>>(p_h);
        k_bnapply<<<(nelem + 255) / 256, 256>>>(p_h, bn1g + bo, bn1b + bo, nullptr);

        k_tgemm<<<dim3(4 * ntiles, mtiles, 1), 256, SMTOT>>>(
            p_xh, p_xl, p_wh + (sb + 5) * WSLOT, p_wl + (sb + 5) * WSLOT,
            p_t, MROWS, CC, CC, ntiles, CC / TK, 0);
        k_edgehalf<<<dim3(NCN, BB), 256>>>(p_t, p_t + XSLOT, p_t + 2 * XSLOT,
                                           p_t + 3 * XSLOT, bu2 + bo, bv2 + bo, p_h);
        k_bnstats<<<CC / 32, dim3(32, 8)>>>(p_h);
        k_bnapply<<<(nelem + 255) / 256, 256>>>(p_h, bn2g + bo, bn2b + bo,
                                                p_t + 4 * XSLOT);
    }

    k_head<<<BB * NCN, 256>>>(fcw, fcb, out);
}

// round 17
// speedup vs baseline: 1.1836x; 1.0166x over previous
#include <cuda_runtime.h>
#include <cuda_bf16.h>
#include <math.h>
#include <stdint.h>

#define BB   4
#define CC   2048
#define PP   196
#define BP   784
#define NCN  200
#define WDD  300
#define INTD 1024
#define NEE  800
#define NL   3
#define EPSV 1e-5f

#define MROWS (BB*NCN)               // 800
#define WSLOT ((size_t)CC*CC)
#define XSLOT ((size_t)MROWS*CC)
#define W1OFF ((size_t)27*WSLOT)

// ---------------- scratch ----------------
__device__ float g_fmap[BP * CC];
__device__ __nv_bfloat16 g_fmh[BP * CC];
__device__ __nv_bfloat16 g_fml[BP * CC];
__device__ float g_fwh [BP * INTD];
__device__ float g_fwd [NCN * INTD];
__device__ float g_wpart[16 * INTD];
__device__ float g_weff[INTD];
__device__ float g_ceff[1];
__device__ float g_coef[BP * NCN];
__device__ __nv_bfloat16 g_xh[XSLOT];
__device__ __nv_bfloat16 g_xl[XSLOT];
__device__ float g_h   [XSLOT];
__device__ float g_t   [5 * XSLOT];
__device__ float g_mean[CC];
__device__ float g_var [CC];
__device__ int   g_es  [NEE];
__device__ int   g_ee  [NEE];
__device__ int   g_eoff[NCN + 1];
__device__ int   g_elist[NEE];
__device__ __nv_bfloat16 g_wbh[27 * WSLOT + (size_t)INTD * CC];
__device__ __nv_bfloat16 g_wbl[27 * WSLOT + (size_t)INTD * CC];

__device__ __forceinline__ float sigm(float x) {
    return 1.0f / (1.0f + __expf(-x));
}

// fma-pipe sigmoid: exact-split exp2 + Newton rcp.
__device__ __forceinline__ float fast_sigm(float x) {
    float t = fminf(fmaxf(x, -30.0f), 30.0f);
    float z = -t * 1.4426950408889634f;
    float zr = z + 12582912.0f;
    int   j  = __float_as_int(zr) - 0x4B400000;
    float f  = z - (zr - 12582912.0f);
    float p = 0.0096181291f;
    p = fmaf(p, f, 0.0555041087f);
    p = fmaf(p, f, 0.2402265069f);
    p = fmaf(p, f, 0.6931471806f);
    p = fmaf(p, f, 1.0f);
    float s = __int_as_float((j + 127) << 23);
    float e = p * s;
    float u = e + 1.0f;
    float r = __int_as_float(0x7EF311C3 - __float_as_int(u));
    r = r * fmaf(-u, r, 2.0f);
    r = r * fmaf(-u, r, 2.0f);
    return r;
}

__device__ __forceinline__ float fast_tanh(float x) {
    float t = fminf(fmaxf(x, -8.0f), 8.0f);
    float z = t * 2.8853900817779268f;
    float zr = z + 12582912.0f;
    int   j  = __float_as_int(zr) - 0x4B400000;
    float f  = z - (zr - 12582912.0f);
    float p = 0.0096181291f;
    p = fmaf(p, f, 0.0555041087f);
    p = fmaf(p, f, 0.2402265069f);
    p = fmaf(p, f, 0.6931471806f);
    p = fmaf(p, f, 1.0f);
    float s = __int_as_float((j + 127) << 23);
    float e = p * s;
    float u = e + 1.0f;
    float r = __int_as_float(0x7EF311C3 - __float_as_int(u));
    r = r * fmaf(-u, r, 2.0f);
    r = r * fmaf(-u, r, 2.0f);
    return (e - 1.0f) * r;
}

__device__ __forceinline__ uint32_t smem_u32(const void* p) {
    uint32_t a;
    asm("{ .reg .u64 t; cvta.to.shared.u64 t, %1; cvt.u32.u64 %0, t; }"
        : "=r"(a) : "l"(p));
    return a;
}

#define LDSM4(R, addr) \
    asm volatile("ldmatrix.sync.aligned.m8n8.x4.shared.b16 {%0,%1,%2,%3}, [%4];" \
        : "=r"((R)[0]), "=r"((R)[1]), "=r"((R)[2]), "=r"((R)[3]) : "r"(addr))

#define MMA16816(C, A, B0, B1) \
    asm volatile("mma.sync.aligned.m16n8k16.row.col.f32.bf16.bf16.f32 " \
        "{%0,%1,%2,%3},{%4,%5,%6,%7},{%8,%9},{%0,%1,%2,%3};" \
        : "+f"((C)[0]), "+f"((C)[1]), "+f"((C)[2]), "+f"((C)[3]) \
        : "r"((A)[0]), "r"((A)[1]), "r"((A)[2]), "r"((A)[3]), "r"(B0), "r"(B1))

#define CP_ASYNC16(dst, src, vld) \
    asm volatile("cp.async.cg.shared.global [%0], [%1], 16, %2;" \
        :: "r"(dst), "l"(src), "r"(vld))
#define CP_COMMIT() asm volatile("cp.async.commit_group;" ::: "memory")
#define CP_WAIT1()  asm volatile("cp.async.wait_group 1;" ::: "memory")
#define CP_WAIT0()  asm volatile("cp.async.wait_group 0;" ::: "memory")

// ============================ HMMA GEMM (frozen champion) ====================
#define TM 128
#define TN 128
#define TK 32
#define MATSZ  (128 * 64)
#define STAGE  (4 * MATSZ)             // 32768
#define NSTG   3
#define SMTOT  (NSTG * STAGE)          // 98304

__device__ __forceinline__ uint32_t swz_off(int row, int g) {
    return (uint32_t)(row * 64 + ((g ^ ((row >> 1) & 3)) << 4));
}

__global__ void __launch_bounds__(256, 2) k_tgemm(
    const __nv_bfloat16* __restrict__ Ah, const __nv_bfloat16* __restrict__ Al,
    const __nv_bfloat16* __restrict__ Wh, const __nv_bfloat16* __restrict__ Wl,
    float* __restrict__ out, int M, int K, int nPerW, int ntilesPerW,
    int nchPerZ, size_t zStride)
{
    extern __shared__ char smem[];
    const uint32_t sbase = smem_u32(smem);
    const int tid  = threadIdx.x;
    const int lane = tid & 31, wid = tid >> 5;
    const int wm = wid >> 2, wn = wid & 3;
    const int widx = blockIdx.x / ntilesPerW;
    const int nt   = blockIdx.x % ntilesPerW;
    const int bm   = blockIdx.y * TM;
    const int kb0  = blockIdx.z * nchPerZ * TK;
    const __nv_bfloat16* Wbh = Wh + (size_t)widx * nPerW * K + (size_t)nt * TN * K;
    const __nv_bfloat16* Wbl = Wl + (size_t)widx * nPerW * K + (size_t)nt * TN * K;
    float* outp = out + (size_t)blockIdx.z * zStride
                      + (size_t)widx * M * nPerW + (size_t)nt * TN;

    float acc[4][4][4];
#pragma unroll
    for (int a = 0; a < 4; a++)
#pragma unroll
        for (int b = 0; b < 4; b++)
#pragma unroll
            for (int c = 0; c < 4; c++) acc[a][b][c] = 0.0f;

    auto load_stage = [&](int ch, int st) {
        const uint32_t so = sbase + st * STAGE;
        const int kb = kb0 + ch * TK;
#pragma unroll
        for (int it = 0; it < 8; it++) {
            int idx = tid + it * 256;
            int mat = idx >> 9;
            int r   = (idx >> 2) & 127;
            int q   = idx & 3;
            const __nv_bfloat16* src;
            int vld = 16;
            if (mat < 2) {
                int gr = bm + r;
                if (gr >= M) { vld = 0; gr = M - 1; }
                src = (mat ? Al : Ah) + (size_t)gr * K + kb + q * 8;
            } else {
                src = (mat == 3 ? Wbl : Wbh) + (size_t)r * K + kb + q * 8;
            }
            uint32_t dst = so + mat * MATSZ + swz_off(r, q);
            CP_ASYNC16(dst, src, vld);
        }
        CP_COMMIT();
    };

    const int a_row0 = wm * 64 + (lane & 15);
    const int a_g    = lane >> 4;
    const int b_row0 = wn * 32 + (lane & 7) + ((lane & 16) ? 8 : 0);
    const int b_g    = (lane & 8) ? 1 : 0;

    auto compute_stage = [&](int st) {
        const uint32_t so = sbase + st * STAGE;
#pragma unroll
        for (int ks = 0; ks < 2; ks++) {
            uint32_t bh[2][4], bl[2][4];
#pragma unroll
            for (int p = 0; p < 2; p++) {
                int row = b_row0 + p * 16;
                uint32_t bd = so + 2 * MATSZ + swz_off(row, ks * 2 + b_g);
                LDSM4(bh[p], bd);
                LDSM4(bl[p], bd + MATSZ);
            }
#pragma unroll
            for (int im = 0; im < 4; im++) {
                int row = a_row0 + im * 16;
                uint32_t ad = so + swz_off(row, ks * 2 + a_g);
                uint32_t ah[4], al[4];
                LDSM4(ah, ad);
                LDSM4(al, ad + MATSZ);
#pragma unroll
                for (int in = 0; in < 4; in++) {
                    int p = in >> 1, s2 = (in & 1) * 2;
                    MMA16816(acc[im][in], ah, bh[p][s2], bh[p][s2 + 1]);
                    MMA16816(acc[im][in], ah, bl[p][s2], bl[p][s2 + 1]);
                    MMA16816(acc[im][in], al, bh[p][s2], bh[p][s2 + 1]);
                }
            }
        }
    };

    const int nch = nchPerZ;
    load_stage(0, 0);
    if (nch > 1) load_stage(1, 1);
    for (int ch = 0; ch < nch; ch++) {
        if (ch + 1 < nch) { CP_WAIT1(); } else { CP_WAIT0(); }
        __syncthreads();
        if (ch + 2 < nch) load_stage(ch + 2, (ch + 2) % NSTG);
        compute_stage(ch % NSTG);
    }

#pragma unroll
    for (int im = 0; im < 4; im++) {
        int r0 = bm + wm * 64 + im * 16 + (lane >> 2);
#pragma unroll
        for (int in = 0; in < 4; in++) {
            int col = wn * 32 + (in >> 1) * 16 + (in & 1) * 8 + (lane & 3) * 2;
            if (r0 < M) {
                float2 v; v.x = acc[im][in][0]; v.y = acc[im][in][1];
                *reinterpret_cast<float2*>(outp + (size_t)r0 * nPerW + col) = v;
            }
            if (r0 + 8 < M) {
                float2 v; v.x = acc[im][in][2]; v.y = acc[im][in][3];
                *reinterpret_cast<float2*>(outp + (size_t)(r0 + 8) * nPerW + col) = v;
            }
        }
    }
}

// split-K reduce for W1
__global__ void k_red4() {
    int i = blockIdx.x * 256 + threadIdx.x;
    const int S4 = BP * INTD / 4;
    if (i >= S4) return;
    const float4* t = reinterpret_cast<const float4*>(g_t);
    float4 a = t[i], b = t[S4 + i], c = t[2 * S4 + i], d = t[3 * S4 + i];
    float4 r;
    r.x = (a.x + b.x) + (c.x + d.x);
    r.y = (a.y + b.y) + (c.y + d.y);
    r.z = (a.z + b.z) + (c.z + d.z);
    r.w = (a.w + b.w) + (c.w + d.w);
    reinterpret_cast<float4*>(g_fwh)[i] = r;
}

// ============================ small kernels ==================================

struct WP27 { const float4* p[27]; };

__device__ __forceinline__ void split4(float4 v, uint2& h2, uint2& l2) {
    __nv_bfloat16 hx = __float2bfloat16(v.x);
    __nv_bfloat16 hy = __float2bfloat16(v.y);
    __nv_bfloat16 hz = __float2bfloat16(v.z);
    __nv_bfloat16 hw = __float2bfloat16(v.w);
    __nv_bfloat162 a = __halves2bfloat162(hx, hy);
    __nv_bfloat162 b = __halves2bfloat162(hz, hw);
    h2.x = *reinterpret_cast<uint32_t*>(&a);
    h2.y = *reinterpret_cast<uint32_t*>(&b);
    __nv_bfloat162 c = __halves2bfloat162(
        __float2bfloat16(v.x - __bfloat162float(hx)),
        __float2bfloat16(v.y - __bfloat162float(hy)));
    __nv_bfloat162 d = __halves2bfloat162(
        __float2bfloat16(v.z - __bfloat162float(hz)),
        __float2bfloat16(v.w - __bfloat162float(hw)));
    l2.x = *reinterpret_cast<uint32_t*>(&c);
    l2.y = *reinterpret_cast<uint32_t*>(&d);
}

__global__ void k_convall(WP27 w) {
    int slot = blockIdx.y;
    size_t i = ((size_t)blockIdx.x * 256 + threadIdx.x) * 4;
    const float4* src = w.p[slot];
    float4 v0 = __ldcs(src + i);
    float4 v1 = __ldcs(src + i + 1);
    float4 v2 = __ldcs(src + i + 2);
    float4 v3 = __ldcs(src + i + 3);
    uint4 ho0, lo0, ho1, lo1;
    uint2 h2, l2;
    split4(v0, h2, l2); ho0.x = h2.x; ho0.y = h2.y; lo0.x = l2.x; lo0.y = l2.y;
    split4(v1, h2, l2); ho0.z = h2.x; ho0.w = h2.y; lo0.z = l2.x; lo0.w = l2.y;
    split4(v2, h2, l2); ho1.x = h2.x; ho1.y = h2.y; lo1.x = l2.x; lo1.y = l2.y;
    split4(v3, h2, l2); ho1.z = h2.x; ho1.w = h2.y; lo1.z = l2.x; lo1.w = l2.y;
    size_t base = (size_t)slot * WSLOT / 8 + i / 2;
    __stcs(reinterpret_cast<uint4*>(g_wbh) + base,     ho0);
    __stcs(reinterpret_cast<uint4*>(g_wbh) + base + 1, ho1);
    __stcs(reinterpret_cast<uint4*>(g_wbl) + base,     lo0);
    __stcs(reinterpret_cast<uint4*>(g_wbl) + base + 1, lo1);
}

__global__ void k_conv(const float4* __restrict__ src,
                       __nv_bfloat16* __restrict__ dh,
                       __nv_bfloat16* __restrict__ dl, int n4)
{
    int i = (blockIdx.x * blockDim.x + threadIdx.x) * 2;
    if (i >= n4) return;
    float4 v0 = __ldcs(src + i);
    float4 v1 = __ldcs(src + i + 1);
    uint4 ho, lo;
    uint2 h2, l2;
    split4(v0, h2, l2); ho.x = h2.x; ho.y = h2.y; lo.x = l2.x; lo.y = l2.y;
    split4(v1, h2, l2); ho.z = h2.x; ho.w = h2.y; lo.z = l2.x; lo.w = l2.y;
    __stcs(reinterpret_cast<uint4*>(dh) + i / 2, ho);
    __stcs(reinterpret_cast<uint4*>(dl) + i / 2, lo);
}

__global__ void k_transpose(const float* __restrict__ img) {
    __shared__ float tile[32][33];
    int b  = blockIdx.z;
    int p0 = blockIdx.x * 32;
    int c0 = blockIdx.y * 32;
    int tx = threadIdx.x, ty = threadIdx.y;
#pragma unroll
    for (int j = 0; j < 4; j++) {
        int c = c0 + ty + j * 8;
        int p = p0 + tx;
        float v = (p < PP) ? img[((size_t)b * CC + c) * PP + p] : 0.0f;
        tile[ty + j * 8][tx] = v;
    }
    __syncthreads();
#pragma unroll
    for (int j = 0; j < 4; j++) {
        int p = p0 + ty + j * 8;
        int c = c0 + tx;
        if (p < PP) {
            float v = tile[tx][ty + j * 8];
            size_t o = ((size_t)b * PP + p) * CC + c;
            g_fmap[o] = v;
            __nv_bfloat16 h = __float2bfloat16(v);
            g_fmh[o] = h;
            g_fml[o] = __float2bfloat16(v - __bfloat162float(h));
        }
    }
}

__global__ __launch_bounds__(256) void k_sgemm(
    const float* __restrict__ A, const float* __restrict__ W,
    float* __restrict__ C, int M, int N, int K)
{
    __shared__ float As[16][65];
    __shared__ float Bs[16][65];
    const int tid = threadIdx.x;
    const int tx = tid & 15, ty = tid >> 4;
    const int bm = blockIdx.y * 64, bn = blockIdx.x * 64;
    const int lr = tid >> 2;
    const int lk = (tid & 3) << 2;

    float acc[4][4];
#pragma unroll
    for (int i = 0; i < 4; i++)
#pragma unroll
        for (int j = 0; j < 4; j++) acc[i][j] = 0.0f;

    for (int k0 = 0; k0 < K; k0 += 16) {
        float a0 = 0, a1 = 0, a2 = 0, a3 = 0;
        int arow = bm + lr;
        if (arow < M) {
            const float* ap = A + (size_t)arow * K + k0 + lk;
            if (k0 + lk + 0 < K) a0 = ap[0];
            if (k0 + lk + 1 < K) a1 = ap[1];
            if (k0 + lk + 2 < K) a2 = ap[2];
            if (k0 + lk + 3 < K) a3 = ap[3];
        }
        As[lk + 0][lr] = a0; As[lk + 1][lr] = a1;
        As[lk + 2][lr] = a2; As[lk + 3][lr] = a3;

        float b0 = 0, b1 = 0, b2 = 0, b3 = 0;
        int wrow = bn + lr;
        if (wrow < N) {
            const float* wp = W + (size_t)wrow * K + k0 + lk;
            if (k0 + lk + 0 < K) b0 = wp[0];
            if (k0 + lk + 1 < K) b1 = wp[1];
            if (k0 + lk + 2 < K) b2 = wp[2];
            if (k0 + lk + 3 < K) b3 = wp[3];
        }
        Bs[lk + 0][lr] = b0; Bs[lk + 1][lr] = b1;
        Bs[lk + 2][lr] = b2; Bs[lk + 3][lr] = b3;

        __syncthreads();
#pragma unroll
        for (int k = 0; k < 16; k++) {
            float av[4], bv[4];
#pragma unroll
            for (int i = 0; i < 4; i++) av[i] = As[k][ty * 4 + i];
#pragma unroll
            for (int j = 0; j < 4; j++) bv[j] = Bs[k][tx * 4 + j];
#pragma unroll
            for (int i = 0; i < 4; i++)
#pragma unroll
                for (int j = 0; j < 4; j++) acc[i][j] += av[i] * bv[j];
        }
        __syncthreads();
    }
#pragma unroll
    for (int i = 0; i < 4; i++) {
        int r = bm + ty * 4 + i;
        if (r >= M) continue;
#pragma unroll
        for (int j = 0; j < 4; j++) {
            int cI = bn + tx * 4 + j;
            if (cI < N) C[(size_t)r * N + cI] = acc[i][j];
        }
    }
}

__global__ void k_weff1(const float* __restrict__ W3, const float* __restrict__ Wa) {
    int i = blockIdx.x * 256 + threadIdx.x;
    int oc = blockIdx.y;
    float s = 0.0f;
    for (int o = oc * 64; o < (oc + 1) * 64; o++)
        s += Wa[o] * W3[(size_t)o * INTD + i];
    g_wpart[oc * INTD + i] = s;
}
__global__ void k_weff2() {
    int i = blockIdx.x * 256 + threadIdx.x;
    float s = 0.0f;
#pragma unroll
    for (int oc = 0; oc < 16; oc++) s += g_wpart[oc * INTD + i];
    g_weff[i] = s;
}

__global__ void k_ceff(const float* __restrict__ Wa, const float* __restrict__ b3,
                       const float* __restrict__ ba) {
    __shared__ float red[256];
    int tid = threadIdx.x;
    float s = 0.0f;
    for (int i = tid; i < INTD; i += 256) s += Wa[i] * b3[i];
    red[tid] = s; __syncthreads();
    for (int st = 128; st > 0; st >>= 1) {
        if (tid < st) red[tid] += red[tid + st];
        __syncthreads();
    }
    if (tid == 0) g_ceff[0] = red[0] + ba[0];
}

// coef: float4 inner loop (8 iters of 4) around the irreducible tanh chain
__global__ __launch_bounds__(256) void k_coef() {
    int bp = blockIdx.x;
    int tid = threadIdx.x;
    __shared__ float s_fwh[INTD];
    __shared__ float s_wef[INTD];
    for (int i = tid; i < INTD; i += 256) {
        s_fwh[i] = g_fwh[(size_t)bp * INTD + i];
        s_wef[i] = g_weff[i];
    }
    __syncthreads();
    int warp = tid >> 5, lane = tid & 31;
    float ce = g_ceff[0];
    const float4* s_fwh4 = reinterpret_cast<const float4*>(s_fwh);
    const float4* s_wef4 = reinterpret_cast<const float4*>(s_wef);
    for (int n = warp; n < NCN; n += 8) {
        const float4* fw4 = reinterpret_cast<const float4*>(g_fwd + (size_t)n * INTD);
        float acc = 0.0f;
#pragma unroll
        for (int it = 0; it < 8; it++) {
            int i4 = lane + it * 32;
            float4 a = s_fwh4[i4];
            float4 wv = s_wef4[i4];
            float4 f = fw4[i4];
            acc += fast_tanh(a.x * f.x) * wv.x;
            acc += fast_tanh(a.y * f.y) * wv.y;
            acc += fast_tanh(a.z * f.z) * wv.z;
            acc += fast_tanh(a.w * f.w) * wv.w;
        }
#pragma unroll
        for (int off = 16; off > 0; off >>= 1)
            acc += __shfl_down_sync(0xffffffffu, acc, off);
        if (lane == 0) g_coef[(size_t)bp * NCN + n] = acc + ce;
    }
}

__global__ __launch_bounds__(256) void k_softmax() {
    int n = blockIdx.x, b = blockIdx.y;
    int tid = threadIdx.x;
    __shared__ float red[256];
    __shared__ float s_mx, s_sum;
    float v = -1e30f;
    if (tid < PP) v = g_coef[((size_t)(b * PP + tid)) * NCN + n];
    red[tid] = v; __syncthreads();
    for (int st = 128; st > 0; st >>= 1) {
        if (tid < st) red[tid] = fmaxf(red[tid], red[tid + st]);
        __syncthreads();
    }
    if (tid == 0) s_mx = red[0];
    __syncthreads();
    float e = 0.0f;
    if (tid < PP) e = __expf(v - s_mx);
    red[tid] = e; __syncthreads();
    for (int st = 128; st > 0; st >>= 1) {
        if (tid < st) red[tid] += red[tid + st];
        __syncthreads();
    }
    if (tid == 0) s_sum = red[0];
    __syncthreads();
    if (tid < PP)
        g_coef[((size_t)(b * PP + tid)) * NCN + n] = e / s_sum;
}

__global__ __launch_bounds__(256) void k_attn() {
    int cb = blockIdx.x * 256;
    int n0 = blockIdx.y * 16;
    int b  = blockIdx.z;
    int tid = threadIdx.x;
    __shared__ float sc[PP * 16];
    for (int i = tid; i < PP * 16; i += 256) {
        int p = i >> 4, j = i & 15;
        int n = n0 + j;
        sc[i] = (n < NCN) ? g_coef[((size_t)(b * PP + p)) * NCN + n] : 0.0f;
    }
    __syncthreads();
    float acc[16];
#pragma unroll
    for (int j = 0; j < 16; j++) acc[j] = 0.0f;
    for (int p = 0; p < PP; p++) {
        float f = g_fmap[((size_t)(b * PP + p)) * CC + cb + tid];
#pragma unroll
        for (int j = 0; j < 16; j++) acc[j] += sc[p * 16 + j] * f;
    }
#pragma unroll
    for (int j = 0; j < 16; j++) {
        int n = n0 + j;
        if (n >= NCN) break;
        size_t o = ((size_t)(b * NCN + n)) * CC + cb + tid;
        float v = acc[j];
        __nv_bfloat16 h = __float2bfloat16(v);
        g_xh[o] = h;
        g_xl[o] = __float2bfloat16(v - __bfloat162float(h));
    }
}

__global__ void k_edgeidx(const float* __restrict__ Es, const float* __restrict__ Ee) {
    int e = blockIdx.x * blockDim.x + threadIdx.x;
    if (e >= NEE) return;
    int si = 0, ei = 0;
    for (int n = 0; n < NCN; n++) {
        if (Es[(size_t)e * NCN + n] > 0.5f) si = n;
        if (Ee[(size_t)e * NCN + n] > 0.5f) ei = n;
    }
    g_es[e] = si;
    g_ee[e] = ei;
}

__global__ void k_edgecsr() {
    __shared__ int see[NEE];
    __shared__ int cnt[NCN];
    __shared__ int off[NCN + 1];
    int tid = threadIdx.x;
    for (int i = tid; i < NEE; i += 256) see[i] = g_ee[i];
    for (int i = tid; i < NCN; i += 256) cnt[i] = 0;
    __syncthreads();
    for (int i = tid; i < NEE; i += 256) atomicAdd(&cnt[see[i]], 1);
    __syncthreads();
    if (tid == 0) {
        off[0] = 0;
        for (int n = 0; n < NCN; n++) off[n + 1] = off[n] + cnt[n];
    }
    __syncthreads();
    for (int e = tid; e < NEE; e += 256) {
        int n = see[e];
        int r = 0;
        for (int e2 = 0; e2 < e; e2++) r += (see[e2] == n) ? 1 : 0;
        g_elist[off[n] + r] = g_es[e];
    }
    for (int i = tid; i <= NCN; i += 256) g_eoff[i] = off[i];
}

// float4-vectorized gated edge aggregation
__global__ __launch_bounds__(256) void k_edgehalf(
    const float* __restrict__ Uix, const float* __restrict__ Ujx,
    const float* __restrict__ Vix, const float* __restrict__ Vjx,
    const float* __restrict__ bu,  const float* __restrict__ bv,
    float* __restrict__ hout)
{
    int n = blockIdx.x, b = blockIdx.y;
    int tid = threadIdx.x;
    int lo = g_eoff[n], hi = g_eoff[n + 1];

    size_t base4 = ((size_t)(b * NCN + n)) * (CC / 4);
    const float4* U4 = reinterpret_cast<const float4*>(Uix) + base4;
    const float4* V4 = reinterpret_cast<const float4*>(Vix) + base4;
    const float4* bu4 = reinterpret_cast<const float4*>(bu);
    const float4* bv4 = reinterpret_cast<const float4*>(bv);
    float4 acc[2], vn[2];
#pragma unroll
    for (int j = 0; j < 2; j++) {
        int c4 = tid + j * 256;
        float4 u = U4[c4], bb = bu4[c4];
        float4 v = V4[c4], vb = bv4[c4];
        acc[j].x = u.x + bb.x; acc[j].y = u.y + bb.y;
        acc[j].z = u.z + bb.z; acc[j].w = u.w + bb.w;
        vn[j].x = v.x + vb.x; vn[j].y = v.y + vb.y;
        vn[j].z = v.z + vb.z; vn[j].w = v.w + vb.w;
    }
    for (int idx = lo; idx < hi; idx++) {
        int se = g_elist[idx];
        size_t b24 = ((size_t)(b * NCN + se)) * (CC / 4);
        const float4* Vj4 = reinterpret_cast<const float4*>(Vjx) + b24;
        const float4* Uj4 = reinterpret_cast<const float4*>(Ujx) + b24;
#pragma unroll
        for (int j = 0; j < 2; j++) {
            int c4 = tid + j * 256;
            float4 vj = Vj4[c4], uj = Uj4[c4];
            acc[j].x += fast_sigm(vn[j].x + vj.x) * uj.x;
            acc[j].y += fast_sigm(vn[j].y + vj.y) * uj.y;
            acc[j].z += fast_sigm(vn[j].z + vj.z) * uj.z;
            acc[j].w += fast_sigm(vn[j].w + vj.w) * uj.w;
        }
    }
    float4* H4 = reinterpret_cast<float4*>(hout) + base4;
#pragma unroll
    for (int j = 0; j < 2; j++) H4[tid + j * 256] = acc[j];
}

__global__ void k_bnstats(const float* __restrict__ h) {
    __shared__ float ssum[8][33];
    __shared__ float ssq [8][33];
    int tx = threadIdx.x;
    int ty = threadIdx.y;
    int c = blockIdx.x * 32 + tx;
    float s = 0.0f, sq = 0.0f;
    for (int r = ty; r < MROWS; r += 8) {
        float v = h[(size_t)r * CC + c];
        s += v; sq += v * v;
    }
    ssum[ty][tx] = s; ssq[ty][tx] = sq;
    __syncthreads();
    if (ty == 0) {
        for (int y = 1; y < 8; y++) { s += ssum[y][tx]; sq += ssq[y][tx]; }
        float m = s / (float)MROWS;
        g_mean[c] = m;
        g_var[c] = sq / (float)MROWS - m * m;
    }
}

// float4 bn apply (+residual) + relu -> packed bf16 hi/lo
__global__ void k_bnapply(const float* __restrict__ h,
                          const float* __restrict__ gamma, const float* __restrict__ beta,
                          const float* __restrict__ res)
{
    int i4 = blockIdx.x * blockDim.x + threadIdx.x;
    if (i4 >= MROWS * CC / 4) return;
    int c4 = i4 & (CC / 4 - 1);
    float4 hv = reinterpret_cast<const float4*>(h)[i4];
    float4 gm = reinterpret_cast<const float4*>(gamma)[c4];
    float4 bt = reinterpret_cast<const float4*>(beta)[c4];
    float4 mn = reinterpret_cast<const float4*>(g_mean)[c4];
    float4 vr = reinterpret_cast<const float4*>(g_var)[c4];
    float4 v;
    v.x = (hv.x - mn.x) * rsqrtf(vr.x + EPSV) * gm.x + bt.x;
    v.y = (hv.y - mn.y) * rsqrtf(vr.y + EPSV) * gm.y + bt.y;
    v.z = (hv.z - mn.z) * rsqrtf(vr.z + EPSV) * gm.z + bt.z;
    v.w = (hv.w - mn.w) * rsqrtf(vr.w + EPSV) * gm.w + bt.w;
    if (res) {
        float4 rv = reinterpret_cast<const float4*>(res)[i4];
        v.x += rv.x; v.y += rv.y; v.z += rv.z; v.w += rv.w;
    }
    v.x = fmaxf(v.x, 0.0f); v.y = fmaxf(v.y, 0.0f);
    v.z = fmaxf(v.z, 0.0f); v.w = fmaxf(v.w, 0.0f);
    uint2 hp, lp;
    split4(v, hp, lp);
    reinterpret_cast<uint2*>(g_xh)[i4] = hp;
    reinterpret_cast<uint2*>(g_xl)[i4] = lp;
}

// head: reconstruct x = hi + lo
__global__ __launch_bounds__(256) void k_head(const float* __restrict__ fcw,
                                              const float* __restrict__ fcb,
                                              float* __restrict__ out)
{
    int bn = blockIdx.x;
    int b = bn / NCN, n = bn % NCN;
    int tid = threadIdx.x;
    __shared__ float red[256];
    const __nv_bfloat16* xh = g_xh + (size_t)bn * CC;
    const __nv_bfloat16* xl = g_xl + (size_t)bn * CC;
    const float* wr = fcw + (size_t)n * CC;
    float s = 0.0f;
    for (int c = tid; c < CC; c += 256) {
        float x = __bfloat162float(xh[c]) + __bfloat162float(xl[c]);
        s += x * wr[c];
    }
    red[tid] = s; __syncthreads();
    for (int st = 128; st > 0; st >>= 1) {
        if (tid < st) red[tid] += red[tid + st];
        __syncthreads();
    }
    if (tid == 0) {
        float v = red[0] + fcb[n];
        float sg = sigm(v);
        if (n < 13) {
            out[b * 13 + n] = sg;
        } else if (n < 51) {
            out[52 + b * 38 + (n - 13)] = sg;
        } else {
            out[204 + b * 149 + (n - 51)] = v;
            out[800 + b * 149 + (n - 51)] = sg;
        }
    }
}

// ================================ launch =====================================
extern "C" void kernel_launch(void* const* d_in, const int* in_sizes, int n_in,
                              void* d_out, int out_size)
{
    const float* img  = (const float*)d_in[0];
    const float* word = (const float*)d_in[1];
    const float* Es   = (const float*)d_in[2];
    const float* Ee   = (const float*)d_in[3];
    const float* W1   = (const float*)d_in[4];
    const float* W2   = (const float*)d_in[5];
    const float* W3   = (const float*)d_in[6];
    const float* b3   = (const float*)d_in[7];
    const float* Wa   = (const float*)d_in[8];
    const float* ba   = (const float*)d_in[9];
    const float* bu1  = (const float*)d_in[19];
    const float* bv1  = (const float*)d_in[20];
    const float* bu2  = (const float*)d_in[21];
    const float* bv2  = (const float*)d_in[22];
    const float* bn1b = (const float*)d_in[23];
    const float* bn2b = (const float*)d_in[24];
    const float* bn1g = (const float*)d_in[25];
    const float* bn2g = (const float*)d_in[26];
    const float* fcw  = (const float*)d_in[27];
    const float* fcb  = (const float*)d_in[28];
    float* out = (float*)d_out;

    const float* wsrc[9] = {
        (const float*)d_in[10], (const float*)d_in[11], (const float*)d_in[12],
        (const float*)d_in[13], (const float*)d_in[18], (const float*)d_in[14],
        (const float*)d_in[15], (const float*)d_in[16], (const float*)d_in[17]
    };

    float *p_fwh, *p_fwd, *p_h, *p_t;
    __nv_bfloat16 *p_fmh, *p_fml, *p_xh, *p_xl, *p_wh, *p_wl;
    cudaGetSymbolAddress((void**)&p_fwh,  g_fwh);
    cudaGetSymbolAddress((void**)&p_fwd,  g_fwd);
    cudaGetSymbolAddress((void**)&p_h,    g_h);
    cudaGetSymbolAddress((void**)&p_t,    g_t);
    cudaGetSymbolAddress((void**)&p_fmh,  g_fmh);
    cudaGetSymbolAddress((void**)&p_fml,  g_fml);
    cudaGetSymbolAddress((void**)&p_xh,   g_xh);
    cudaGetSymbolAddress((void**)&p_xl,   g_xl);
    cudaGetSymbolAddress((void**)&p_wh,   g_wbh);
    cudaGetSymbolAddress((void**)&p_wl,   g_wbl);

    cudaFuncSetAttribute(k_tgemm, cudaFuncAttributeMaxDynamicSharedMemorySize,
                         SMTOT);

    // 1) fmap transpose + bf16 split
    k_transpose<<<dim3((PP + 31) / 32, CC / 32, BB), dim3(32, 8)>>>(img);

    // 2) weight conversions
    {
        WP27 wp;
        for (int l = 0; l < NL; l++)
            for (int s = 0; s < 9; s++)
                wp.p[l * 9 + s] = (const float4*)(wsrc[s] + (size_t)l * WSLOT);
        k_convall<<<dim3((int)(WSLOT / 16 / 256), 27), 256>>>(wp);
    }
    k_conv<<<(INTD * CC / 8 + 255) / 256, 256>>>(
        (const float4*)W1, p_wh + W1OFF, p_wl + W1OFF, INTD * CC / 4);

    // 3) f_wh via split-K=4
    k_tgemm<<<dim3(INTD / TN, (BP + TM - 1) / TM, 4), 256, SMTOT>>>(
        p_fmh, p_fml, p_wh + W1OFF, p_wl + W1OFF, p_t,
        BP, CC, INTD, INTD / TN, CC / TK / 4, (size_t)BP * INTD);
    k_red4<<<(BP * INTD / 4 + 255) / 256, 256>>>();

    // 4) f_wd
    k_sgemm<<<dim3((INTD + 63) / 64, (NCN + 63) / 64), 256>>>(word, W2, p_fwd,
                                                              NCN, INTD, WDD);
    // 5) collapsed attention weights
    k_weff1<<<dim3(INTD / 256, 16), 256>>>(W3, Wa);
    k_weff2<<<INTD / 256, 256>>>();
    k_ceff<<<1, 256>>>(Wa, b3, ba);

    // 6) attention
    k_coef<<<BP, 256>>>();
    k_softmax<<<dim3(NCN, BB), 256>>>();
    k_attn<<<dim3(CC / 256, (NCN + 15) / 16, BB), 256>>>();

    // 7) edges
    k_edgeidx<<<(NEE + 255) / 256, 256>>>(Es, Ee);
    k_edgecsr<<<1, 256>>>();

    const int nelem4 = MROWS * CC / 4;
    const int mtiles = (MROWS + TM - 1) / TM;   // 7
    const int ntiles = CC / TN;                 // 16

    for (int l = 0; l < NL; l++) {
        size_t sb = (size_t)l * 9;
        size_t bo = (size_t)l * CC;

        k_tgemm<<<dim3(5 * ntiles, mtiles, 1), 256, SMTOT>>>(
            p_xh, p_xl, p_wh + sb * WSLOT, p_wl + sb * WSLOT,
            p_t, MROWS, CC, CC, ntiles, CC / TK, 0);
        k_edgehalf<<<dim3(NCN, BB), 256>>>(p_t, p_t + XSLOT, p_t + 2 * XSLOT,
                                           p_t + 3 * XSLOT, bu1 + bo, bv1 + bo, p_h);
        k_bnstats<<<CC / 32, dim3(32, 8)>>>(p_h);
        k_bnapply<<<(nelem4 + 255) / 256, 256>>>(p_h, bn1g + bo, bn1b + bo, nullptr);

        k_tgemm<<<dim3(4 * ntiles, mtiles, 1), 256, SMTOT>>>(
            p_xh, p_xl, p_wh + (sb + 5) * WSLOT, p_wl + (sb + 5) * WSLOT,
            p_t, MROWS, CC, CC, ntiles, CC / TK, 0);
        k_edgehalf<<<dim3(NCN, BB), 256>>>(p_t, p_t + XSLOT, p_t + 2 * XSLOT,
                                           p_t + 3 * XSLOT, bu2 + bo, bv2 + bo, p_h);
        k_bnstats<<<CC / 32, dim3(32, 8)>>>(p_h);
        k_bnapply<<<(nelem4 + 255) / 256, 256>>>(p_h, bn2g + bo, bn2b + bo,
                                                 p_t + 4 * XSLOT);
    }

    k_head<<<BB * NCN, 256>>>(fcw, fcb, out);
}